// round 12
// baseline (speedup 1.0000x reference)
#include <cuda_runtime.h>
#include <cuda_bf16.h>
#include <cuda_fp16.h>
#include <cstdint>

#define NN   50000
#define EE   800000
#define FIN  128
#define H1   8
#define C1   32
#define HC   256
#define CO   10
#define NG   128
#define NEG_SLOPE 0.2f
#define NBLK 196          // ceil(NN/256)

// ---------------- scratch ----------------------------------------------------
__device__ uint8_t        g_xh8[(size_t)NN * HC];   // layer1 feats (e4m3)
__device__ __nv_bfloat16  g_h1b[(size_t)NN * HC];   // layer1 out post-elu (bf16)
__device__ __nv_bfloat16  g_w1b[(size_t)HC * FIN];
__device__ float g_as1[NN * H1];
__device__ float g_ad1[NN * H1];
__device__ int   g_deg[NN];
__device__ int   g_off[NN + 1];
__device__ int   g_cur[NN];
__device__ int   g_part[NBLK];
__device__ int   g_ssrc[EE];
__device__ float g_xh2[(size_t)NN * 16];
__device__ float g_as2[NN];
__device__ float g_ad2[NN];
__device__ float g_sums[NG * CO];
__device__ float g_cnt[NG];

__device__ __forceinline__ float elu(float x) {
    return x > 0.0f ? x : (__expf(x) - 1.0f);
}
// exp(leaky_relu(x, 0.2)) = 2^(0.6*log2e*x + 0.4*log2e*|x|)
__device__ __forceinline__ float exp_lrelu(float x) {
    float t = fmaf(0.57707802f, fabsf(x), 0.86561702f * x);
    float w;
    asm("ex2.approx.f32 %0, %1;" : "=f"(w) : "f"(t));
    return w;
}
__device__ __forceinline__ void mma16816(float* d, const uint32_t* a, const uint32_t* b) {
    asm volatile(
        "mma.sync.aligned.m16n8k16.row.col.f32.bf16.bf16.f32 "
        "{%0,%1,%2,%3}, {%4,%5,%6,%7}, {%8,%9}, {%0,%1,%2,%3};"
        : "+f"(d[0]), "+f"(d[1]), "+f"(d[2]), "+f"(d[3])
        : "r"(a[0]), "r"(a[1]), "r"(a[2]), "r"(a[3]), "r"(b[0]), "r"(b[1]));
}
__device__ __forceinline__ void ldsm4(uint32_t& r0, uint32_t& r1, uint32_t& r2,
                                      uint32_t& r3, uint32_t addr) {
    asm volatile("ldmatrix.sync.aligned.m8n8.x4.shared.b16 {%0,%1,%2,%3}, [%4];"
                 : "=r"(r0), "=r"(r1), "=r"(r2), "=r"(r3) : "r"(addr));
}
__device__ __forceinline__ uint16_t pack_e4m3(float lo, float hi) {
    uint16_t p;
    asm("cvt.rn.satfinite.e4m3x2.f32 %0, %1, %2;" : "=h"(p) : "f"(hi), "f"(lo));
    return p;
}
__device__ __forceinline__ __half2 e4m3_to_h2(uint16_t b) {
    uint32_t r;
    asm("cvt.rn.f16x2.e4m3x2 %0, %1;" : "=r"(r) : "h"(b));
    return *(__half2*)&r;
}

// ---------------- 0. zero ----------------------------------------------------
__global__ void k_zero() {
    int i = blockIdx.x * blockDim.x + threadIdx.x;
    if (i < NN) g_deg[i] = 0;
    if (i < NG * CO) g_sums[i] = 0.0f;
    if (i < NG) g_cnt[i] = 0.0f;
}

// ---------------- W1 transpose+convert ----------------------------------------
__global__ void k_cvt_w(const float* __restrict__ W1) {
    __shared__ float s[32][33];
    int k0 = blockIdx.x * 32;
    int n0 = blockIdx.y * 32;
    int tx = threadIdx.x, ty = threadIdx.y;
    s[ty][tx] = W1[(size_t)(k0 + ty) * HC + n0 + tx];
    __syncthreads();
    g_w1b[(size_t)(n0 + ty) * FIN + k0 + tx] = __float2bfloat16(s[tx][ty]);
}

// ---------------- GEMM1 HMMA + ldmatrix: CTA tile 64x256, K=128 ----------------
#define G1_ST   136
#define G1_ST2  (G1_ST * 2)
#define G1_ASZ  (64 * G1_ST2)
#define G1_SMEM (G1_ASZ + 256 * G1_ST2)
__global__ void __launch_bounds__(256, 2) k_gemm1(const float* __restrict__ x,
                                                  const float* __restrict__ att_src,
                                                  const float* __restrict__ att_dst) {
    extern __shared__ char smem[];
    char* sA = smem;
    char* sB = smem + G1_ASZ;
    const int tid = threadIdx.x;
    const int wid = tid >> 5;
    const int lane = tid & 31;
    const int bm = blockIdx.x * 64;
    const int mw = wid >> 2;
    const int nw = wid & 3;
    const int g = lane >> 2;
    const int t2 = (lane & 3) * 2;

#pragma unroll
    for (int i = 0; i < 8; i++) {
        int idx = tid + i * 256;
        int row = idx >> 5;
        int c4 = idx & 31;
        float4 v = make_float4(0.f, 0.f, 0.f, 0.f);
        int grow = bm + row;
        if (grow < NN) v = *(const float4*)(x + (size_t)grow * FIN + c4 * 4);
        __nv_bfloat162 b0 = __floats2bfloat162_rn(v.x, v.y);
        __nv_bfloat162 b1 = __floats2bfloat162_rn(v.z, v.w);
        uint2 p = make_uint2(*(uint32_t*)&b0, *(uint32_t*)&b1);
        *(uint2*)(sA + row * G1_ST2 + c4 * 8) = p;
    }
#pragma unroll
    for (int i = 0; i < 16; i++) {
        int idx = tid + i * 256;
        int row = idx >> 4;
        int c16 = idx & 15;
        uint4 v = *(const uint4*)(g_w1b + (size_t)row * FIN + c16 * 8);
        *(uint4*)(sB + row * G1_ST2 + c16 * 16) = v;
    }
    __syncthreads();

    const uint32_t sAu = (uint32_t)__cvta_generic_to_shared(sA);
    const uint32_t sBu = (uint32_t)__cvta_generic_to_shared(sB);
    const int l15 = lane & 15;
    const int kgA = ((lane >> 4) & 1) * 16;
    uint32_t aAddr[2];
#pragma unroll
    for (int mt = 0; mt < 2; mt++)
        aAddr[mt] = sAu + (mw * 32 + mt * 16 + l15) * G1_ST2 + kgA;
    const int rB = (lane & 7) + ((lane >> 4) & 1) * 8;
    const int kgB = ((lane >> 3) & 1) * 16;
    uint32_t bAddr[4];
#pragma unroll
    for (int jp = 0; jp < 4; jp++)
        bAddr[jp] = sBu + (nw * 64 + jp * 16 + rB) * G1_ST2 + kgB;

    float acc[2][8][4];
#pragma unroll
    for (int mt = 0; mt < 2; mt++)
#pragma unroll
        for (int j = 0; j < 8; j++)
#pragma unroll
            for (int q = 0; q < 4; q++) acc[mt][j][q] = 0.f;

#pragma unroll
    for (int kk = 0; kk < 8; kk++) {
        const uint32_t ko = kk * 32;
        uint32_t afr[2][4];
#pragma unroll
        for (int mt = 0; mt < 2; mt++)
            ldsm4(afr[mt][0], afr[mt][1], afr[mt][2], afr[mt][3], aAddr[mt] + ko);
        uint32_t bfr[8][2];
#pragma unroll
        for (int jp = 0; jp < 4; jp++)
            ldsm4(bfr[2 * jp][0], bfr[2 * jp][1], bfr[2 * jp + 1][0], bfr[2 * jp + 1][1],
                  bAddr[jp] + ko);
#pragma unroll
        for (int mt = 0; mt < 2; mt++)
#pragma unroll
            for (int j = 0; j < 8; j++) mma16816(acc[mt][j], afr[mt], bfr[j]);
    }

#pragma unroll
    for (int mt = 0; mt < 2; mt++) {
        const int r0 = bm + mw * 32 + mt * 16 + g;
        const int r1 = r0 + 8;
        // fp8 stores (message payload)
#pragma unroll
        for (int j = 0; j < 8; j++) {
            const int c = nw * 64 + j * 8 + t2;
            uint16_t p0 = pack_e4m3(acc[mt][j][0], acc[mt][j][1]);
            uint16_t p1 = pack_e4m3(acc[mt][j][2], acc[mt][j][3]);
            if (r0 < NN) *(uint16_t*)(g_xh8 + (size_t)r0 * HC + c) = p0;
            if (r1 < NN) *(uint16_t*)(g_xh8 + (size_t)r1 * HC + c) = p1;
        }
        // attention logits (fp32 accumulators — full precision)
#pragma unroll
        for (int hh = 0; hh < 2; hh++) {
            float ps0 = 0.f, pd0 = 0.f, ps1 = 0.f, pd1 = 0.f;
#pragma unroll
            for (int jj = 0; jj < 4; jj++) {
                const int j = hh * 4 + jj;
                const int c = nw * 64 + j * 8 + t2;
                float2 s2 = *(const float2*)(att_src + c);
                float2 d2 = *(const float2*)(att_dst + c);
                ps0 = fmaf(acc[mt][j][0], s2.x, fmaf(acc[mt][j][1], s2.y, ps0));
                pd0 = fmaf(acc[mt][j][0], d2.x, fmaf(acc[mt][j][1], d2.y, pd0));
                ps1 = fmaf(acc[mt][j][2], s2.x, fmaf(acc[mt][j][3], s2.y, ps1));
                pd1 = fmaf(acc[mt][j][2], d2.x, fmaf(acc[mt][j][3], d2.y, pd1));
            }
            ps0 += __shfl_xor_sync(0xffffffffu, ps0, 1);
            pd0 += __shfl_xor_sync(0xffffffffu, pd0, 1);
            ps1 += __shfl_xor_sync(0xffffffffu, ps1, 1);
            pd1 += __shfl_xor_sync(0xffffffffu, pd1, 1);
            ps0 += __shfl_xor_sync(0xffffffffu, ps0, 2);
            pd0 += __shfl_xor_sync(0xffffffffu, pd0, 2);
            ps1 += __shfl_xor_sync(0xffffffffu, ps1, 2);
            pd1 += __shfl_xor_sync(0xffffffffu, pd1, 2);
            const int h = nw * 2 + hh;
            if ((lane & 3) == 0) {
                if (r0 < NN) { g_as1[r0 * H1 + h] = ps0; g_ad1[r0 * H1 + h] = pd0; }
                if (r1 < NN) { g_as1[r1 * H1 + h] = ps1; g_ad1[r1 * H1 + h] = pd1; }
            }
        }
    }
}

// ---------------- CSR build ----------------------------------------------------
__global__ void k_hist(const int* __restrict__ ei, int E) {
    int e = blockIdx.x * blockDim.x + threadIdx.x;
    if (e < E) atomicAdd(&g_deg[ei[E + e]], 1);
}
__global__ void k_scan1() {
    __shared__ int s[256];
    int i = blockIdx.x * 256 + threadIdx.x;
    int v = (i < NN) ? g_deg[i] : 0;
    s[threadIdx.x] = v;
    __syncthreads();
    for (int o = 128; o; o >>= 1) {
        if (threadIdx.x < o) s[threadIdx.x] += s[threadIdx.x + o];
        __syncthreads();
    }
    if (threadIdx.x == 0) g_part[blockIdx.x] = s[0];
}
__global__ void k_scan2() {
    __shared__ int s[256];
    int t = threadIdx.x;
    int v = (t < NBLK) ? g_part[t] : 0;
    s[t] = v;
    __syncthreads();
    for (int o = 1; o < 256; o <<= 1) {
        int u = (t >= o) ? s[t - o] : 0;
        __syncthreads();
        s[t] += u;
        __syncthreads();
    }
    if (t < NBLK) g_part[t] = s[t] - v;
}
__global__ void k_scan3() {
    __shared__ int s[256];
    int t = threadIdx.x;
    int i = blockIdx.x * 256 + t;
    int v = (i < NN) ? g_deg[i] : 0;
    s[t] = v;
    __syncthreads();
    for (int o = 1; o < 256; o <<= 1) {
        int u = (t >= o) ? s[t - o] : 0;
        __syncthreads();
        s[t] += u;
        __syncthreads();
    }
    int base = g_part[blockIdx.x];
    if (i < NN) {
        int off = base + s[t] - v;
        g_off[i] = off;
        g_cur[i] = off;
        if (i == NN - 1) g_off[NN] = base + s[t];
    }
}
__global__ void k_scatter(const int* __restrict__ ei, int E) {
    int e = blockIdx.x * blockDim.x + threadIdx.x;
    if (e < E) {
        int d = ei[E + e];
        int p = atomicAdd(&g_cur[d], 1);
        g_ssrc[p] = ei[e];
    }
}

// ---------------- layer-1 aggregation: fp8 gather, fp16 HFMA2 accumulate --------
__device__ __forceinline__ void edge_acc1(int s, float ad, int h, int vidx,
                                          const uint2* x8, __half2* acc, float& wsum) {
    const float a = g_as1[s * H1 + h];
    const uint2 v = x8[(size_t)s * 32 + vidx];
    const float w = exp_lrelu(a + ad);
    wsum += w;
    const __half2 w2 = __float2half2_rn(w);
    acc[0] = __hfma2(w2, e4m3_to_h2((uint16_t)(v.x & 0xffff)), acc[0]);
    acc[1] = __hfma2(w2, e4m3_to_h2((uint16_t)(v.x >> 16)), acc[1]);
    acc[2] = __hfma2(w2, e4m3_to_h2((uint16_t)(v.y & 0xffff)), acc[2]);
    acc[3] = __hfma2(w2, e4m3_to_h2((uint16_t)(v.y >> 16)), acc[3]);
}

__global__ void k_agg1(const float* __restrict__ b1) {
    const int warp = threadIdx.x >> 5;
    const int lane = threadIdx.x & 31;
    const int nA = (blockIdx.x * 8 + warp) * 2;
    const int nB = nA + 1;
    const int h = lane >> 2;
    const int q = lane & 3;
    const int vidx = h * 4 + q;                 // uint2 index; 8 channels/lane
    const uint2* x8 = (const uint2*)g_xh8;

    const float adA = g_ad1[nA * H1 + h];
    const float adB = g_ad1[nB * H1 + h];
    __half2 accA[4], accB[4];
    float wsumA, wsumB;
    {   // self loops
        float wA = exp_lrelu(g_as1[nA * H1 + h] + adA);
        float wB = exp_lrelu(g_as1[nB * H1 + h] + adB);
        wsumA = wA; wsumB = wB;
        __half2 wA2 = __float2half2_rn(wA);
        __half2 wB2 = __float2half2_rn(wB);
        uint2 vA = x8[(size_t)nA * 32 + vidx];
        uint2 vB = x8[(size_t)nB * 32 + vidx];
        accA[0] = __hmul2(wA2, e4m3_to_h2((uint16_t)(vA.x & 0xffff)));
        accA[1] = __hmul2(wA2, e4m3_to_h2((uint16_t)(vA.x >> 16)));
        accA[2] = __hmul2(wA2, e4m3_to_h2((uint16_t)(vA.y & 0xffff)));
        accA[3] = __hmul2(wA2, e4m3_to_h2((uint16_t)(vA.y >> 16)));
        accB[0] = __hmul2(wB2, e4m3_to_h2((uint16_t)(vB.x & 0xffff)));
        accB[1] = __hmul2(wB2, e4m3_to_h2((uint16_t)(vB.x >> 16)));
        accB[2] = __hmul2(wB2, e4m3_to_h2((uint16_t)(vB.y & 0xffff)));
        accB[3] = __hmul2(wB2, e4m3_to_h2((uint16_t)(vB.y >> 16)));
    }

    int eA = g_off[nA];
    const int endA = g_off[nA + 1];
    int eB = endA;
    const int endB = g_off[nB + 1];

    while (eA + 2 <= endA && eB + 2 <= endB) {
        const int sA0 = g_ssrc[eA], sA1 = g_ssrc[eA + 1];
        const int sB0 = g_ssrc[eB], sB1 = g_ssrc[eB + 1];
        edge_acc1(sA0, adA, h, vidx, x8, accA, wsumA);
        edge_acc1(sB0, adB, h, vidx, x8, accB, wsumB);
        edge_acc1(sA1, adA, h, vidx, x8, accA, wsumA);
        edge_acc1(sB1, adB, h, vidx, x8, accB, wsumB);
        eA += 2; eB += 2;
    }
    for (; eA + 2 <= endA; eA += 2) {
        const int s0 = g_ssrc[eA], s1 = g_ssrc[eA + 1];
        edge_acc1(s0, adA, h, vidx, x8, accA, wsumA);
        edge_acc1(s1, adA, h, vidx, x8, accA, wsumA);
    }
    for (; eB + 2 <= endB; eB += 2) {
        const int s0 = g_ssrc[eB], s1 = g_ssrc[eB + 1];
        edge_acc1(s0, adB, h, vidx, x8, accB, wsumB);
        edge_acc1(s1, adB, h, vidx, x8, accB, wsumB);
    }
    if (eA < endA) edge_acc1(g_ssrc[eA], adA, h, vidx, x8, accA, wsumA);
    if (eB < endB) edge_acc1(g_ssrc[eB], adB, h, vidx, x8, accB, wsumB);

    // epilogue: fp32 normalize + bias + elu + bf16 store
    const int c0 = h * C1 + q * 8;
    float bias[8];
#pragma unroll
    for (int j = 0; j < 8; j++) bias[j] = b1[c0 + j];
    const float invA = 1.0f / wsumA;
    const float invB = 1.0f / wsumB;
    __nv_bfloat162 obA[4], obB[4];
#pragma unroll
    for (int j = 0; j < 4; j++) {
        float2 fA = __half22float2(accA[j]);
        float2 fB = __half22float2(accB[j]);
        obA[j] = __floats2bfloat162_rn(elu(fA.x * invA + bias[2 * j]),
                                       elu(fA.y * invA + bias[2 * j + 1]));
        obB[j] = __floats2bfloat162_rn(elu(fB.x * invB + bias[2 * j]),
                                       elu(fB.y * invB + bias[2 * j + 1]));
    }
    ((uint4*)g_h1b)[(size_t)nA * 32 + vidx] = *(uint4*)obA;
    ((uint4*)g_h1b)[(size_t)nB * 32 + vidx] = *(uint4*)obB;
}

// ---------------- GEMM2 HMMA: 128x16x256, fused attention epilogue --------------
#define G2_ST   264
#define G2_ASZ  (128 * G2_ST * 2)
#define G2_BSZ  (16 * G2_ST * 2)
#define G2_SMEM (G2_ASZ + G2_BSZ)
__global__ void __launch_bounds__(256, 2) k_gemm2(const float* __restrict__ W2,
                                                  const float* __restrict__ att_src2,
                                                  const float* __restrict__ att_dst2) {
    extern __shared__ char smem[];
    char* sA = smem;
    char* sB = smem + G2_ASZ;
    const int tid = threadIdx.x;
    const int wid = tid >> 5;
    const int lane = tid & 31;
    const int bm = blockIdx.x * 128;
    const int g = lane >> 2;
    const int t2 = (lane & 3) * 2;

    for (int i = tid; i < G2_BSZ / 4; i += 256) ((uint32_t*)sB)[i] = 0;
#pragma unroll
    for (int i = 0; i < 16; i++) {
        int idx = tid + i * 256;
        int row = idx >> 5;
        int c16 = idx & 31;
        int grow = bm + row;
        uint4 v = make_uint4(0, 0, 0, 0);
        if (grow < NN) v = *(const uint4*)(g_h1b + (size_t)grow * HC + c16 * 8);
        *(uint4*)(sA + row * (G2_ST * 2) + c16 * 16) = v;
    }
    __syncthreads();
    for (int idx = tid; idx < HC * CO; idx += 256) {
        int k = idx / CO;
        int n = idx % CO;
        ((__nv_bfloat16*)sB)[n * G2_ST + k] = __float2bfloat16(W2[idx]);
    }
    __syncthreads();

    float a0c[4] = {0.f, 0.f, 0.f, 0.f};
    float a1c[4] = {0.f, 0.f, 0.f, 0.f};
#pragma unroll
    for (int kk = 0; kk < 16; kk++) {
        const int k0 = kk * 16;
        const int rb = wid * 16;
        uint32_t afr[4];
        afr[0] = *(const uint32_t*)(sA + (rb + g) * (G2_ST * 2) + (k0 + t2) * 2);
        afr[1] = *(const uint32_t*)(sA + (rb + g + 8) * (G2_ST * 2) + (k0 + t2) * 2);
        afr[2] = *(const uint32_t*)(sA + (rb + g) * (G2_ST * 2) + (k0 + 8 + t2) * 2);
        afr[3] = *(const uint32_t*)(sA + (rb + g + 8) * (G2_ST * 2) + (k0 + 8 + t2) * 2);
        uint32_t b0[2], b1[2];
        b0[0] = *(const uint32_t*)(sB + g * (G2_ST * 2) + (k0 + t2) * 2);
        b0[1] = *(const uint32_t*)(sB + g * (G2_ST * 2) + (k0 + 8 + t2) * 2);
        b1[0] = *(const uint32_t*)(sB + (8 + g) * (G2_ST * 2) + (k0 + t2) * 2);
        b1[1] = *(const uint32_t*)(sB + (8 + g) * (G2_ST * 2) + (k0 + 8 + t2) * 2);
        mma16816(a0c, afr, b0);
        mma16816(a1c, afr, b1);
    }

    const int r0 = bm + wid * 16 + g;
    const int r1 = r0 + 8;
    if (r0 < NN) {
        *(float2*)(g_xh2 + (size_t)r0 * 16 + t2) = make_float2(a0c[0], a0c[1]);
        *(float2*)(g_xh2 + (size_t)r0 * 16 + 8 + t2) = make_float2(a1c[0], a1c[1]);
    }
    if (r1 < NN) {
        *(float2*)(g_xh2 + (size_t)r1 * 16 + t2) = make_float2(a0c[2], a0c[3]);
        *(float2*)(g_xh2 + (size_t)r1 * 16 + 8 + t2) = make_float2(a1c[2], a1c[3]);
    }
    float s0x = att_src2[t2], s0y = att_src2[t2 + 1];
    float d0x = att_dst2[t2], d0y = att_dst2[t2 + 1];
    float s1x = 0.f, s1y = 0.f, d1x = 0.f, d1y = 0.f;
    if (t2 == 0) { s1x = att_src2[8]; s1y = att_src2[9]; d1x = att_dst2[8]; d1y = att_dst2[9]; }
    float ps0 = a0c[0] * s0x + a0c[1] * s0y + a1c[0] * s1x + a1c[1] * s1y;
    float pd0 = a0c[0] * d0x + a0c[1] * d0y + a1c[0] * d1x + a1c[1] * d1y;
    float ps1 = a0c[2] * s0x + a0c[3] * s0y + a1c[2] * s1x + a1c[3] * s1y;
    float pd1 = a0c[2] * d0x + a0c[3] * d0y + a1c[2] * d1x + a1c[3] * d1y;
    ps0 += __shfl_xor_sync(0xffffffffu, ps0, 1);
    pd0 += __shfl_xor_sync(0xffffffffu, pd0, 1);
    ps1 += __shfl_xor_sync(0xffffffffu, ps1, 1);
    pd1 += __shfl_xor_sync(0xffffffffu, pd1, 1);
    ps0 += __shfl_xor_sync(0xffffffffu, ps0, 2);
    pd0 += __shfl_xor_sync(0xffffffffu, pd0, 2);
    ps1 += __shfl_xor_sync(0xffffffffu, ps1, 2);
    pd1 += __shfl_xor_sync(0xffffffffu, pd1, 2);
    if ((lane & 3) == 0) {
        if (r0 < NN) { g_as2[r0] = ps0; g_ad2[r0] = pd0; }
        if (r1 < NN) { g_as2[r1] = ps1; g_ad2[r1] = pd1; }
    }
}

// ---------------- layer-2 aggregation ---------------------------------------------
__global__ void k_agg2(const int* __restrict__ batch, const float* __restrict__ b2) {
    int warp = threadIdx.x >> 5;
    int lane = threadIdx.x & 31;
    int n = blockIdx.x * 8 + warp;
    if (n >= NN) return;
    const int half = lane >> 4;
    const int i = lane & 15;
    const float ad = g_ad2[n];
    float wsum = 0.f, acc = 0.f;
    if (half == 0) {
        float w = exp_lrelu(g_as2[n] + ad);
        wsum = w;
        acc = w * g_xh2[(size_t)n * 16 + i];
    }
    const int beg = g_off[n], end = g_off[n + 1];
    for (int e = beg + half; e < end; e += 2) {
        const int s = g_ssrc[e];
        const float we = exp_lrelu(g_as2[s] + ad);
        wsum += we;
        acc = fmaf(we, g_xh2[(size_t)s * 16 + i], acc);
    }
    wsum += __shfl_xor_sync(0xffffffffu, wsum, 16);
    acc += __shfl_xor_sync(0xffffffffu, acc, 16);
    if (half == 0 && i < CO) {
        float out = elu(acc / wsum + b2[i]);
        atomicAdd(&g_sums[batch[n] * CO + i], out);
    }
    if (lane == 0) atomicAdd(&g_cnt[batch[n]], 1.0f);
}

// ---------------- mean + log_softmax ----------------------------------------------
__global__ void k_final(float* __restrict__ out) {
    int g = threadIdx.x;
    if (g >= NG) return;
    float inv = 1.0f / fmaxf(g_cnt[g], 1.0f);
    float v[CO];
    float mx = -1e30f;
#pragma unroll
    for (int c = 0; c < CO; c++) {
        v[c] = g_sums[g * CO + c] * inv;
        mx = fmaxf(mx, v[c]);
    }
    float s = 0.f;
#pragma unroll
    for (int c = 0; c < CO; c++) s += __expf(v[c] - mx);
    float lse = logf(s) + mx;
#pragma unroll
    for (int c = 0; c < CO; c++) out[g * CO + c] = v[c] - lse;
}

// ---------------- launcher ----------------------------------------------------------
extern "C" void kernel_launch(void* const* d_in, const int* in_sizes, int n_in,
                              void* d_out, int out_size) {
    const float* x        = (const float*)d_in[0];
    const int*   ei       = (const int*)d_in[1];
    const int*   batch    = (const int*)d_in[2];
    const float* W1       = (const float*)d_in[3];
    const float* att_src1 = (const float*)d_in[4];
    const float* att_dst1 = (const float*)d_in[5];
    const float* b1       = (const float*)d_in[6];
    const float* W2       = (const float*)d_in[7];
    const float* att_src2 = (const float*)d_in[8];
    const float* att_dst2 = (const float*)d_in[9];
    const float* b2       = (const float*)d_in[10];
    float* out = (float*)d_out;
    const int E = in_sizes[1] / 2;

    static cudaStream_t s1 = nullptr;
    static cudaEvent_t e0 = nullptr, e1 = nullptr;
    if (!s1) {
        cudaStreamCreateWithFlags(&s1, cudaStreamNonBlocking);
        cudaEventCreateWithFlags(&e0, cudaEventDisableTiming);
        cudaEventCreateWithFlags(&e1, cudaEventDisableTiming);
        cudaFuncSetAttribute(k_gemm1, cudaFuncAttributeMaxDynamicSharedMemorySize, G1_SMEM);
        cudaFuncSetAttribute(k_gemm2, cudaFuncAttributeMaxDynamicSharedMemorySize, G2_SMEM);
    }

    cudaEventRecord(e0, 0);
    k_zero<<<(NN + 255) / 256, 256>>>();
    k_hist<<<(E + 255) / 256, 256>>>(ei, E);
    cudaStreamWaitEvent(s1, e0, 0);
    k_cvt_w<<<dim3(FIN / 32, HC / 32), dim3(32, 32), 0, s1>>>(W1);
    k_gemm1<<<(NN + 63) / 64, 256, G1_SMEM, s1>>>(x, att_src1, att_dst1);
    cudaEventRecord(e1, s1);
    k_scan1<<<NBLK, 256>>>();
    k_scan2<<<1, 256>>>();
    k_scan3<<<NBLK, 256>>>();
    k_scatter<<<(E + 255) / 256, 256>>>(ei, E);
    cudaStreamWaitEvent(0, e1, 0);
    k_agg1<<<NN / 16, 256>>>(b1);
    k_gemm2<<<(NN + 127) / 128, 256, G2_SMEM>>>(W2, att_src2, att_dst2);
    k_agg2<<<(NN + 7) / 8, 256>>>(batch, b2);
    k_final<<<1, NG>>>(out);
}

// round 13
// speedup vs baseline: 1.0244x; 1.0244x over previous
#include <cuda_runtime.h>
#include <cuda_bf16.h>
#include <cstdint>

#define NN   50000
#define EE   800000
#define FIN  128
#define H1   8
#define C1   32
#define HC   256
#define CO   10
#define NG   128
#define NEG_SLOPE 0.2f
#define NBLK 196          // ceil(NN/256)

// ---------------- scratch ----------------------------------------------------
__device__ __nv_bfloat16  g_xhb[(size_t)NN * HC];
__device__ __nv_bfloat16  g_h1b[(size_t)NN * HC];
__device__ __nv_bfloat16  g_w1b[(size_t)HC * FIN];
__device__ float g_as1[NN * H1];
__device__ float g_ad1[NN * H1];
__device__ int   g_deg[NN];
__device__ int   g_off[NN + 1];
__device__ int   g_cur[NN];
__device__ int   g_part[NBLK];
__device__ int   g_ssrc[EE];
__device__ float g_xh2[(size_t)NN * 16];
__device__ float g_as2[NN];
__device__ float g_ad2[NN];
__device__ float g_sums[NG * CO];
__device__ float g_cnt[NG];

__device__ __forceinline__ float elu(float x) {
    return x > 0.0f ? x : (__expf(x) - 1.0f);
}
// exp(leaky_relu(x, 0.2)) = 2^(0.6*log2e*x + 0.4*log2e*|x|)
__device__ __forceinline__ float exp_lrelu(float x) {
    float t = fmaf(0.57707802f, fabsf(x), 0.86561702f * x);
    float w;
    asm("ex2.approx.f32 %0, %1;" : "=f"(w) : "f"(t));
    return w;
}
__device__ __forceinline__ void mma16816(float* d, const uint32_t* a, const uint32_t* b) {
    asm volatile(
        "mma.sync.aligned.m16n8k16.row.col.f32.bf16.bf16.f32 "
        "{%0,%1,%2,%3}, {%4,%5,%6,%7}, {%8,%9}, {%0,%1,%2,%3};"
        : "+f"(d[0]), "+f"(d[1]), "+f"(d[2]), "+f"(d[3])
        : "r"(a[0]), "r"(a[1]), "r"(a[2]), "r"(a[3]), "r"(b[0]), "r"(b[1]));
}
__device__ __forceinline__ void ldsm4(uint32_t& r0, uint32_t& r1, uint32_t& r2,
                                      uint32_t& r3, uint32_t addr) {
    asm volatile("ldmatrix.sync.aligned.m8n8.x4.shared.b16 {%0,%1,%2,%3}, [%4];"
                 : "=r"(r0), "=r"(r1), "=r"(r2), "=r"(r3) : "r"(addr));
}

// ---------------- 0. zero ----------------------------------------------------
__global__ void k_zero() {
    int i = blockIdx.x * blockDim.x + threadIdx.x;
    if (i < NN) g_deg[i] = 0;
    if (i < NG * CO) g_sums[i] = 0.0f;
    if (i < NG) g_cnt[i] = 0.0f;
}

// ---------------- W1 transpose+convert ----------------------------------------
__global__ void k_cvt_w(const float* __restrict__ W1) {
    __shared__ float s[32][33];
    int k0 = blockIdx.x * 32;
    int n0 = blockIdx.y * 32;
    int tx = threadIdx.x, ty = threadIdx.y;
    s[ty][tx] = W1[(size_t)(k0 + ty) * HC + n0 + tx];
    __syncthreads();
    g_w1b[(size_t)(n0 + ty) * FIN + k0 + tx] = __float2bfloat16(s[tx][ty]);
}

// ---------------- GEMM1 HMMA + ldmatrix: CTA tile 64x256, K=128 ----------------
#define G1_ST   136
#define G1_ST2  (G1_ST * 2)
#define G1_ASZ  (64 * G1_ST2)
#define G1_SMEM (G1_ASZ + 256 * G1_ST2)
__global__ void __launch_bounds__(256, 2) k_gemm1(const float* __restrict__ x,
                                                  const float* __restrict__ att_src,
                                                  const float* __restrict__ att_dst) {
    extern __shared__ char smem[];
    char* sA = smem;
    char* sB = smem + G1_ASZ;
    const int tid = threadIdx.x;
    const int wid = tid >> 5;
    const int lane = tid & 31;
    const int bm = blockIdx.x * 64;
    const int mw = wid >> 2;
    const int nw = wid & 3;
    const int g = lane >> 2;
    const int t2 = (lane & 3) * 2;

#pragma unroll
    for (int i = 0; i < 8; i++) {
        int idx = tid + i * 256;
        int row = idx >> 5;
        int c4 = idx & 31;
        float4 v = make_float4(0.f, 0.f, 0.f, 0.f);
        int grow = bm + row;
        if (grow < NN) v = *(const float4*)(x + (size_t)grow * FIN + c4 * 4);
        __nv_bfloat162 b0 = __floats2bfloat162_rn(v.x, v.y);
        __nv_bfloat162 b1 = __floats2bfloat162_rn(v.z, v.w);
        uint2 p = make_uint2(*(uint32_t*)&b0, *(uint32_t*)&b1);
        *(uint2*)(sA + row * G1_ST2 + c4 * 8) = p;
    }
#pragma unroll
    for (int i = 0; i < 16; i++) {
        int idx = tid + i * 256;
        int row = idx >> 4;
        int c16 = idx & 15;
        uint4 v = *(const uint4*)(g_w1b + (size_t)row * FIN + c16 * 8);
        *(uint4*)(sB + row * G1_ST2 + c16 * 16) = v;
    }
    __syncthreads();

    const uint32_t sAu = (uint32_t)__cvta_generic_to_shared(sA);
    const uint32_t sBu = (uint32_t)__cvta_generic_to_shared(sB);
    const int l15 = lane & 15;
    const int kgA = ((lane >> 4) & 1) * 16;
    uint32_t aAddr[2];
#pragma unroll
    for (int mt = 0; mt < 2; mt++)
        aAddr[mt] = sAu + (mw * 32 + mt * 16 + l15) * G1_ST2 + kgA;
    const int rB = (lane & 7) + ((lane >> 4) & 1) * 8;
    const int kgB = ((lane >> 3) & 1) * 16;
    uint32_t bAddr[4];
#pragma unroll
    for (int jp = 0; jp < 4; jp++)
        bAddr[jp] = sBu + (nw * 64 + jp * 16 + rB) * G1_ST2 + kgB;

    float acc[2][8][4];
#pragma unroll
    for (int mt = 0; mt < 2; mt++)
#pragma unroll
        for (int j = 0; j < 8; j++)
#pragma unroll
            for (int q = 0; q < 4; q++) acc[mt][j][q] = 0.f;

#pragma unroll
    for (int kk = 0; kk < 8; kk++) {
        const uint32_t ko = kk * 32;
        uint32_t afr[2][4];
#pragma unroll
        for (int mt = 0; mt < 2; mt++)
            ldsm4(afr[mt][0], afr[mt][1], afr[mt][2], afr[mt][3], aAddr[mt] + ko);
        uint32_t bfr[8][2];
#pragma unroll
        for (int jp = 0; jp < 4; jp++)
            ldsm4(bfr[2 * jp][0], bfr[2 * jp][1], bfr[2 * jp + 1][0], bfr[2 * jp + 1][1],
                  bAddr[jp] + ko);
#pragma unroll
        for (int mt = 0; mt < 2; mt++)
#pragma unroll
            for (int j = 0; j < 8; j++) mma16816(acc[mt][j], afr[mt], bfr[j]);
    }

#pragma unroll
    for (int mt = 0; mt < 2; mt++) {
        const int r0 = bm + mw * 32 + mt * 16 + g;
        const int r1 = r0 + 8;
#pragma unroll
        for (int j = 0; j < 8; j++) {
            const int c = nw * 64 + j * 8 + t2;
            __nv_bfloat162 v0 = __floats2bfloat162_rn(acc[mt][j][0], acc[mt][j][1]);
            __nv_bfloat162 v1 = __floats2bfloat162_rn(acc[mt][j][2], acc[mt][j][3]);
            if (r0 < NN) *(uint32_t*)(g_xhb + (size_t)r0 * HC + c) = *(uint32_t*)&v0;
            if (r1 < NN) *(uint32_t*)(g_xhb + (size_t)r1 * HC + c) = *(uint32_t*)&v1;
        }
#pragma unroll
        for (int hh = 0; hh < 2; hh++) {
            float ps0 = 0.f, pd0 = 0.f, ps1 = 0.f, pd1 = 0.f;
#pragma unroll
            for (int jj = 0; jj < 4; jj++) {
                const int j = hh * 4 + jj;
                const int c = nw * 64 + j * 8 + t2;
                float2 s2 = *(const float2*)(att_src + c);
                float2 d2 = *(const float2*)(att_dst + c);
                ps0 = fmaf(acc[mt][j][0], s2.x, fmaf(acc[mt][j][1], s2.y, ps0));
                pd0 = fmaf(acc[mt][j][0], d2.x, fmaf(acc[mt][j][1], d2.y, pd0));
                ps1 = fmaf(acc[mt][j][2], s2.x, fmaf(acc[mt][j][3], s2.y, ps1));
                pd1 = fmaf(acc[mt][j][2], d2.x, fmaf(acc[mt][j][3], d2.y, pd1));
            }
            ps0 += __shfl_xor_sync(0xffffffffu, ps0, 1);
            pd0 += __shfl_xor_sync(0xffffffffu, pd0, 1);
            ps1 += __shfl_xor_sync(0xffffffffu, ps1, 1);
            pd1 += __shfl_xor_sync(0xffffffffu, pd1, 1);
            ps0 += __shfl_xor_sync(0xffffffffu, ps0, 2);
            pd0 += __shfl_xor_sync(0xffffffffu, pd0, 2);
            ps1 += __shfl_xor_sync(0xffffffffu, ps1, 2);
            pd1 += __shfl_xor_sync(0xffffffffu, pd1, 2);
            const int h = nw * 2 + hh;
            if ((lane & 3) == 0) {
                if (r0 < NN) { g_as1[r0 * H1 + h] = ps0; g_ad1[r0 * H1 + h] = pd0; }
                if (r1 < NN) { g_as1[r1 * H1 + h] = ps1; g_ad1[r1 * H1 + h] = pd1; }
            }
        }
    }
}

// ---------------- CSR build ----------------------------------------------------
__global__ void k_hist(const int* __restrict__ ei, int E) {
    int e = blockIdx.x * blockDim.x + threadIdx.x;
    if (e < E) atomicAdd(&g_deg[ei[E + e]], 1);
}
__global__ void k_scan1() {
    __shared__ int s[256];
    int i = blockIdx.x * 256 + threadIdx.x;
    int v = (i < NN) ? g_deg[i] : 0;
    s[threadIdx.x] = v;
    __syncthreads();
    for (int o = 128; o; o >>= 1) {
        if (threadIdx.x < o) s[threadIdx.x] += s[threadIdx.x + o];
        __syncthreads();
    }
    if (threadIdx.x == 0) g_part[blockIdx.x] = s[0];
}
__global__ void k_scan2() {
    __shared__ int s[256];
    int t = threadIdx.x;
    int v = (t < NBLK) ? g_part[t] : 0;
    s[t] = v;
    __syncthreads();
    for (int o = 1; o < 256; o <<= 1) {
        int u = (t >= o) ? s[t - o] : 0;
        __syncthreads();
        s[t] += u;
        __syncthreads();
    }
    if (t < NBLK) g_part[t] = s[t] - v;
}
__global__ void k_scan3() {
    __shared__ int s[256];
    int t = threadIdx.x;
    int i = blockIdx.x * 256 + t;
    int v = (i < NN) ? g_deg[i] : 0;
    s[t] = v;
    __syncthreads();
    for (int o = 1; o < 256; o <<= 1) {
        int u = (t >= o) ? s[t - o] : 0;
        __syncthreads();
        s[t] += u;
        __syncthreads();
    }
    int base = g_part[blockIdx.x];
    if (i < NN) {
        int off = base + s[t] - v;
        g_off[i] = off;
        g_cur[i] = off;
        if (i == NN - 1) g_off[NN] = base + s[t];
    }
}
__global__ void k_scatter(const int* __restrict__ ei, int E) {
    int e = blockIdx.x * blockDim.x + threadIdx.x;
    if (e < E) {
        int d = ei[E + e];
        int p = atomicAdd(&g_cur[d], 1);
        g_ssrc[p] = ei[e];
    }
}

// ---------------- layer-1 aggregation: bf16 HFMA2, index-pipelined --------------
__device__ __forceinline__ void edge_acc1(int s, float ad, int h, int vidx,
                                          const uint4* xb, __nv_bfloat162* acc,
                                          float& wsum) {
    const float a = g_as1[s * H1 + h];
    const uint4 v = xb[(size_t)s * 32 + vidx];
    const float w = exp_lrelu(a + ad);
    wsum += w;
    const __nv_bfloat162 w2 = __float2bfloat162_rn(w);
    const __nv_bfloat162* p = (const __nv_bfloat162*)&v;
#pragma unroll
    for (int j = 0; j < 4; j++) acc[j] = __hfma2(w2, p[j], acc[j]);
}

__global__ void k_agg1(const float* __restrict__ b1) {
    const int warp = threadIdx.x >> 5;
    const int lane = threadIdx.x & 31;
    const int nA = (blockIdx.x * 8 + warp) * 2;
    const int nB = nA + 1;
    const int h = lane >> 2;
    const int q = lane & 3;
    const int vidx = h * 4 + q;
    const uint4* xb = (const uint4*)g_xhb;

    const float adA = g_ad1[nA * H1 + h];
    const float adB = g_ad1[nB * H1 + h];
    __nv_bfloat162 accA[4], accB[4];
    float wsumA, wsumB;
    {   // self loops
        float wA = exp_lrelu(g_as1[nA * H1 + h] + adA);
        float wB = exp_lrelu(g_as1[nB * H1 + h] + adB);
        wsumA = wA; wsumB = wB;
        __nv_bfloat162 wA2 = __float2bfloat162_rn(wA);
        __nv_bfloat162 wB2 = __float2bfloat162_rn(wB);
        uint4 vA = xb[(size_t)nA * 32 + vidx];
        uint4 vB = xb[(size_t)nB * 32 + vidx];
        const __nv_bfloat162* pA = (const __nv_bfloat162*)&vA;
        const __nv_bfloat162* pB = (const __nv_bfloat162*)&vB;
#pragma unroll
        for (int j = 0; j < 4; j++) {
            accA[j] = __hmul2(wA2, pA[j]);
            accB[j] = __hmul2(wB2, pB[j]);
        }
    }

    int eA = g_off[nA];
    const int endA = g_off[nA + 1];
    int eB = endA;
    const int endB = g_off[nB + 1];

    // software-pipelined main loop: indices for iteration t+1 prefetched during t
    int pA0 = 0, pA1 = 0, pB0 = 0, pB1 = 0;
    bool more = (eA + 2 <= endA) && (eB + 2 <= endB);
    if (more) {
        pA0 = g_ssrc[eA]; pA1 = g_ssrc[eA + 1];
        pB0 = g_ssrc[eB]; pB1 = g_ssrc[eB + 1];
    }
    while (more) {
        const int cA0 = pA0, cA1 = pA1, cB0 = pB0, cB1 = pB1;
        eA += 2; eB += 2;
        more = (eA + 2 <= endA) && (eB + 2 <= endB);
        if (more) {
            pA0 = g_ssrc[eA]; pA1 = g_ssrc[eA + 1];
            pB0 = g_ssrc[eB]; pB1 = g_ssrc[eB + 1];
        }
        edge_acc1(cA0, adA, h, vidx, xb, accA, wsumA);
        edge_acc1(cB0, adB, h, vidx, xb, accB, wsumB);
        edge_acc1(cA1, adA, h, vidx, xb, accA, wsumA);
        edge_acc1(cB1, adB, h, vidx, xb, accB, wsumB);
    }
    for (; eA + 2 <= endA; eA += 2) {
        const int s0 = g_ssrc[eA], s1 = g_ssrc[eA + 1];
        edge_acc1(s0, adA, h, vidx, xb, accA, wsumA);
        edge_acc1(s1, adA, h, vidx, xb, accA, wsumA);
    }
    for (; eB + 2 <= endB; eB += 2) {
        const int s0 = g_ssrc[eB], s1 = g_ssrc[eB + 1];
        edge_acc1(s0, adB, h, vidx, xb, accB, wsumB);
        edge_acc1(s1, adB, h, vidx, xb, accB, wsumB);
    }
    if (eA < endA) edge_acc1(g_ssrc[eA], adA, h, vidx, xb, accA, wsumA);
    if (eB < endB) edge_acc1(g_ssrc[eB], adB, h, vidx, xb, accB, wsumB);

    // epilogue
    const int c0 = h * C1 + q * 8;
    float bias[8];
#pragma unroll
    for (int j = 0; j < 8; j++) bias[j] = b1[c0 + j];
    const float invA = 1.0f / wsumA;
    const float invB = 1.0f / wsumB;
    __nv_bfloat162 obA[4], obB[4];
#pragma unroll
    for (int j = 0; j < 4; j++) {
        float2 fA = __bfloat1622float2(accA[j]);
        float2 fB = __bfloat1622float2(accB[j]);
        obA[j] = __floats2bfloat162_rn(elu(fA.x * invA + bias[2 * j]),
                                       elu(fA.y * invA + bias[2 * j + 1]));
        obB[j] = __floats2bfloat162_rn(elu(fB.x * invB + bias[2 * j]),
                                       elu(fB.y * invB + bias[2 * j + 1]));
    }
    ((uint4*)g_h1b)[(size_t)nA * 32 + vidx] = *(uint4*)obA;
    ((uint4*)g_h1b)[(size_t)nB * 32 + vidx] = *(uint4*)obB;
}

// ---------------- GEMM2 HMMA: 128x16x256, fused attention epilogue --------------
#define G2_ST   264
#define G2_ASZ  (128 * G2_ST * 2)
#define G2_BSZ  (16 * G2_ST * 2)
#define G2_SMEM (G2_ASZ + G2_BSZ)
__global__ void __launch_bounds__(256, 2) k_gemm2(const float* __restrict__ W2,
                                                  const float* __restrict__ att_src2,
                                                  const float* __restrict__ att_dst2) {
    extern __shared__ char smem[];
    char* sA = smem;
    char* sB = smem + G2_ASZ;
    const int tid = threadIdx.x;
    const int wid = tid >> 5;
    const int lane = tid & 31;
    const int bm = blockIdx.x * 128;
    const int g = lane >> 2;
    const int t2 = (lane & 3) * 2;

    for (int i = tid; i < G2_BSZ / 4; i += 256) ((uint32_t*)sB)[i] = 0;
#pragma unroll
    for (int i = 0; i < 16; i++) {
        int idx = tid + i * 256;
        int row = idx >> 5;
        int c16 = idx & 31;
        int grow = bm + row;
        uint4 v = make_uint4(0, 0, 0, 0);
        if (grow < NN) v = *(const uint4*)(g_h1b + (size_t)grow * HC + c16 * 8);
        *(uint4*)(sA + row * (G2_ST * 2) + c16 * 16) = v;
    }
    __syncthreads();
    for (int idx = tid; idx < HC * CO; idx += 256) {
        int k = idx / CO;
        int n = idx % CO;
        ((__nv_bfloat16*)sB)[n * G2_ST + k] = __float2bfloat16(W2[idx]);
    }
    __syncthreads();

    float a0c[4] = {0.f, 0.f, 0.f, 0.f};
    float a1c[4] = {0.f, 0.f, 0.f, 0.f};
#pragma unroll
    for (int kk = 0; kk < 16; kk++) {
        const int k0 = kk * 16;
        const int rb = wid * 16;
        uint32_t afr[4];
        afr[0] = *(const uint32_t*)(sA + (rb + g) * (G2_ST * 2) + (k0 + t2) * 2);
        afr[1] = *(const uint32_t*)(sA + (rb + g + 8) * (G2_ST * 2) + (k0 + t2) * 2);
        afr[2] = *(const uint32_t*)(sA + (rb + g) * (G2_ST * 2) + (k0 + 8 + t2) * 2);
        afr[3] = *(const uint32_t*)(sA + (rb + g + 8) * (G2_ST * 2) + (k0 + 8 + t2) * 2);
        uint32_t b0[2], b1[2];
        b0[0] = *(const uint32_t*)(sB + g * (G2_ST * 2) + (k0 + t2) * 2);
        b0[1] = *(const uint32_t*)(sB + g * (G2_ST * 2) + (k0 + 8 + t2) * 2);
        b1[0] = *(const uint32_t*)(sB + (8 + g) * (G2_ST * 2) + (k0 + t2) * 2);
        b1[1] = *(const uint32_t*)(sB + (8 + g) * (G2_ST * 2) + (k0 + 8 + t2) * 2);
        mma16816(a0c, afr, b0);
        mma16816(a1c, afr, b1);
    }

    const int r0 = bm + wid * 16 + g;
    const int r1 = r0 + 8;
    if (r0 < NN) {
        *(float2*)(g_xh2 + (size_t)r0 * 16 + t2) = make_float2(a0c[0], a0c[1]);
        *(float2*)(g_xh2 + (size_t)r0 * 16 + 8 + t2) = make_float2(a1c[0], a1c[1]);
    }
    if (r1 < NN) {
        *(float2*)(g_xh2 + (size_t)r1 * 16 + t2) = make_float2(a0c[2], a0c[3]);
        *(float2*)(g_xh2 + (size_t)r1 * 16 + 8 + t2) = make_float2(a1c[2], a1c[3]);
    }
    float s0x = att_src2[t2], s0y = att_src2[t2 + 1];
    float d0x = att_dst2[t2], d0y = att_dst2[t2 + 1];
    float s1x = 0.f, s1y = 0.f, d1x = 0.f, d1y = 0.f;
    if (t2 == 0) { s1x = att_src2[8]; s1y = att_src2[9]; d1x = att_dst2[8]; d1y = att_dst2[9]; }
    float ps0 = a0c[0] * s0x + a0c[1] * s0y + a1c[0] * s1x + a1c[1] * s1y;
    float pd0 = a0c[0] * d0x + a0c[1] * d0y + a1c[0] * d1x + a1c[1] * d1y;
    float ps1 = a0c[2] * s0x + a0c[3] * s0y + a1c[2] * s1x + a1c[3] * s1y;
    float pd1 = a0c[2] * d0x + a0c[3] * d0y + a1c[2] * d1x + a1c[3] * d1y;
    ps0 += __shfl_xor_sync(0xffffffffu, ps0, 1);
    pd0 += __shfl_xor_sync(0xffffffffu, pd0, 1);
    ps1 += __shfl_xor_sync(0xffffffffu, ps1, 1);
    pd1 += __shfl_xor_sync(0xffffffffu, pd1, 1);
    ps0 += __shfl_xor_sync(0xffffffffu, ps0, 2);
    pd0 += __shfl_xor_sync(0xffffffffu, pd0, 2);
    ps1 += __shfl_xor_sync(0xffffffffu, ps1, 2);
    pd1 += __shfl_xor_sync(0xffffffffu, pd1, 2);
    if ((lane & 3) == 0) {
        if (r0 < NN) { g_as2[r0] = ps0; g_ad2[r0] = pd0; }
        if (r1 < NN) { g_as2[r1] = ps1; g_ad2[r1] = pd1; }
    }
}

// ---------------- layer-2 aggregation: halves + unroll2 + index prefetch --------
__global__ void k_agg2(const int* __restrict__ batch, const float* __restrict__ b2) {
    int warp = threadIdx.x >> 5;
    int lane = threadIdx.x & 31;
    int n = blockIdx.x * 8 + warp;
    if (n >= NN) return;
    const int half = lane >> 4;
    const int i = lane & 15;
    const float ad = g_ad2[n];
    float wsum = 0.f, acc = 0.f;
    if (half == 0) {
        float w = exp_lrelu(g_as2[n] + ad);
        wsum = w;
        acc = w * g_xh2[(size_t)n * 16 + i];
    }
    const int beg = g_off[n], end = g_off[n + 1];
    int e = beg + half;
    int p0 = 0, p1 = 0;
    bool more = (e + 2 < end);
    if (more) { p0 = g_ssrc[e]; p1 = g_ssrc[e + 2]; }
    while (more) {
        const int c0 = p0, c1 = p1;
        e += 4;
        more = (e + 2 < end);
        if (more) { p0 = g_ssrc[e]; p1 = g_ssrc[e + 2]; }
        const float w0 = exp_lrelu(g_as2[c0] + ad);
        const float w1 = exp_lrelu(g_as2[c1] + ad);
        const float v0 = g_xh2[(size_t)c0 * 16 + i];
        const float v1 = g_xh2[(size_t)c1 * 16 + i];
        wsum += w0 + w1;
        acc = fmaf(w0, v0, fmaf(w1, v1, acc));
    }
    for (; e < end; e += 2) {
        const int s = g_ssrc[e];
        const float we = exp_lrelu(g_as2[s] + ad);
        wsum += we;
        acc = fmaf(we, g_xh2[(size_t)s * 16 + i], acc);
    }
    wsum += __shfl_xor_sync(0xffffffffu, wsum, 16);
    acc += __shfl_xor_sync(0xffffffffu, acc, 16);
    if (half == 0 && i < CO) {
        float out = elu(acc / wsum + b2[i]);
        atomicAdd(&g_sums[batch[n] * CO + i], out);
    }
    if (lane == 0) atomicAdd(&g_cnt[batch[n]], 1.0f);
}

// ---------------- mean + log_softmax ----------------------------------------------
__global__ void k_final(float* __restrict__ out) {
    int g = threadIdx.x;
    if (g >= NG) return;
    float inv = 1.0f / fmaxf(g_cnt[g], 1.0f);
    float v[CO];
    float mx = -1e30f;
#pragma unroll
    for (int c = 0; c < CO; c++) {
        v[c] = g_sums[g * CO + c] * inv;
        mx = fmaxf(mx, v[c]);
    }
    float s = 0.f;
#pragma unroll
    for (int c = 0; c < CO; c++) s += __expf(v[c] - mx);
    float lse = logf(s) + mx;
#pragma unroll
    for (int c = 0; c < CO; c++) out[g * CO + c] = v[c] - lse;
}

// ---------------- launcher ----------------------------------------------------------
extern "C" void kernel_launch(void* const* d_in, const int* in_sizes, int n_in,
                              void* d_out, int out_size) {
    const float* x        = (const float*)d_in[0];
    const int*   ei       = (const int*)d_in[1];
    const int*   batch    = (const int*)d_in[2];
    const float* W1       = (const float*)d_in[3];
    const float* att_src1 = (const float*)d_in[4];
    const float* att_dst1 = (const float*)d_in[5];
    const float* b1       = (const float*)d_in[6];
    const float* W2       = (const float*)d_in[7];
    const float* att_src2 = (const float*)d_in[8];
    const float* att_dst2 = (const float*)d_in[9];
    const float* b2       = (const float*)d_in[10];
    float* out = (float*)d_out;
    const int E = in_sizes[1] / 2;

    static cudaStream_t s1 = nullptr;
    static cudaEvent_t e0 = nullptr, e1 = nullptr;
    if (!s1) {
        cudaStreamCreateWithFlags(&s1, cudaStreamNonBlocking);
        cudaEventCreateWithFlags(&e0, cudaEventDisableTiming);
        cudaEventCreateWithFlags(&e1, cudaEventDisableTiming);
        cudaFuncSetAttribute(k_gemm1, cudaFuncAttributeMaxDynamicSharedMemorySize, G1_SMEM);
        cudaFuncSetAttribute(k_gemm2, cudaFuncAttributeMaxDynamicSharedMemorySize, G2_SMEM);
    }

    cudaEventRecord(e0, 0);
    k_zero<<<(NN + 255) / 256, 256>>>();
    k_hist<<<(E + 255) / 256, 256>>>(ei, E);
    cudaStreamWaitEvent(s1, e0, 0);
    k_cvt_w<<<dim3(FIN / 32, HC / 32), dim3(32, 32), 0, s1>>>(W1);
    k_gemm1<<<(NN + 63) / 64, 256, G1_SMEM, s1>>>(x, att_src1, att_dst1);
    cudaEventRecord(e1, s1);
    k_scan1<<<NBLK, 256>>>();
    k_scan2<<<1, 256>>>();
    k_scan3<<<NBLK, 256>>>();
    k_scatter<<<(E + 255) / 256, 256>>>(ei, E);
    cudaStreamWaitEvent(0, e1, 0);
    k_agg1<<<NN / 16, 256>>>(b1);
    k_gemm2<<<(NN + 127) / 128, 256, G2_SMEM>>>(W2, att_src2, att_dst2);
    k_agg2<<<(NN + 7) / 8, 256>>>(batch, b2);
    k_final<<<1, NG>>>(out);
}

// round 15
// speedup vs baseline: 1.0300x; 1.0054x over previous
#include <cuda_runtime.h>
#include <cuda_bf16.h>
#include <cstdint>

#define NN   50000
#define EE   800000
#define FIN  128
#define H1   8
#define C1   32
#define HC   256
#define CO   10
#define NG   128
#define NEG_SLOPE 0.2f
#define NBLK 196          // ceil(NN/256)

// ---------------- scratch ----------------------------------------------------
__device__ __nv_bfloat16  g_xhb[(size_t)NN * HC];
__device__ __nv_bfloat16  g_h1b[(size_t)NN * HC];
__device__ __nv_bfloat16  g_w1b[(size_t)HC * FIN];
__device__ float g_as1[NN * H1];
__device__ float g_ad1[NN * H1];
__device__ int   g_deg[NN];
__device__ int   g_off[NN + 1];
__device__ int   g_cur[NN];
__device__ int   g_part[NBLK];
__device__ int   g_ssrc[EE];
__device__ float g_xh2[(size_t)NN * 16];
__device__ float g_as2[NN];
__device__ float g_ad2[NN];
__device__ float g_sums[NG * CO];
__device__ float g_cnt[NG];

__device__ __forceinline__ float elu(float x) {
    return x > 0.0f ? x : (__expf(x) - 1.0f);
}
// exp(leaky_relu(x, 0.2)) = 2^(0.6*log2e*x + 0.4*log2e*|x|)
__device__ __forceinline__ float exp_lrelu(float x) {
    float t = fmaf(0.57707802f, fabsf(x), 0.86561702f * x);
    float w;
    asm("ex2.approx.f32 %0, %1;" : "=f"(w) : "f"(t));
    return w;
}
__device__ __forceinline__ void mma16816(float* d, const uint32_t* a, const uint32_t* b) {
    asm volatile(
        "mma.sync.aligned.m16n8k16.row.col.f32.bf16.bf16.f32 "
        "{%0,%1,%2,%3}, {%4,%5,%6,%7}, {%8,%9}, {%0,%1,%2,%3};"
        : "+f"(d[0]), "+f"(d[1]), "+f"(d[2]), "+f"(d[3])
        : "r"(a[0]), "r"(a[1]), "r"(a[2]), "r"(a[3]), "r"(b[0]), "r"(b[1]));
}
__device__ __forceinline__ void ldsm4(uint32_t& r0, uint32_t& r1, uint32_t& r2,
                                      uint32_t& r3, uint32_t addr) {
    asm volatile("ldmatrix.sync.aligned.m8n8.x4.shared.b16 {%0,%1,%2,%3}, [%4];"
                 : "=r"(r0), "=r"(r1), "=r"(r2), "=r"(r3) : "r"(addr));
}

// ---------------- 0. zero (deg + pooled accumulators, full coverage) -----------
__global__ void k_zero() {
    int i = blockIdx.x * blockDim.x + threadIdx.x;
    if (i < NN) g_deg[i] = 0;
    if (i < NG * CO) g_sums[i] = 0.0f;
    if (i < NG) g_cnt[i] = 0.0f;
}

// ---------------- W1 transpose+convert ----------------------------------------
__global__ void k_cvt_w(const float* __restrict__ W1) {
    __shared__ float s[32][33];
    int k0 = blockIdx.x * 32;
    int n0 = blockIdx.y * 32;
    int tx = threadIdx.x, ty = threadIdx.y;
    s[ty][tx] = W1[(size_t)(k0 + ty) * HC + n0 + tx];
    __syncthreads();
    g_w1b[(size_t)(n0 + ty) * FIN + k0 + tx] = __float2bfloat16(s[tx][ty]);
}

// ---------------- GEMM1 HMMA + ldmatrix: CTA tile 64x256, K=128 ----------------
#define G1_ST   136
#define G1_ST2  (G1_ST * 2)
#define G1_ASZ  (64 * G1_ST2)
#define G1_SMEM (G1_ASZ + 256 * G1_ST2)
__global__ void __launch_bounds__(256, 2) k_gemm1(const float* __restrict__ x,
                                                  const float* __restrict__ att_src,
                                                  const float* __restrict__ att_dst) {
    extern __shared__ char smem[];
    char* sA = smem;
    char* sB = smem + G1_ASZ;
    const int tid = threadIdx.x;
    const int wid = tid >> 5;
    const int lane = tid & 31;
    const int bm = blockIdx.x * 64;
    const int mw = wid >> 2;
    const int nw = wid & 3;
    const int g = lane >> 2;
    const int t2 = (lane & 3) * 2;

#pragma unroll
    for (int i = 0; i < 8; i++) {
        int idx = tid + i * 256;
        int row = idx >> 5;
        int c4 = idx & 31;
        float4 v = make_float4(0.f, 0.f, 0.f, 0.f);
        int grow = bm + row;
        if (grow < NN) v = *(const float4*)(x + (size_t)grow * FIN + c4 * 4);
        __nv_bfloat162 b0 = __floats2bfloat162_rn(v.x, v.y);
        __nv_bfloat162 b1 = __floats2bfloat162_rn(v.z, v.w);
        uint2 p = make_uint2(*(uint32_t*)&b0, *(uint32_t*)&b1);
        *(uint2*)(sA + row * G1_ST2 + c4 * 8) = p;
    }
#pragma unroll
    for (int i = 0; i < 16; i++) {
        int idx = tid + i * 256;
        int row = idx >> 4;
        int c16 = idx & 15;
        uint4 v = *(const uint4*)(g_w1b + (size_t)row * FIN + c16 * 8);
        *(uint4*)(sB + row * G1_ST2 + c16 * 16) = v;
    }
    __syncthreads();

    const uint32_t sAu = (uint32_t)__cvta_generic_to_shared(sA);
    const uint32_t sBu = (uint32_t)__cvta_generic_to_shared(sB);
    const int l15 = lane & 15;
    const int kgA = ((lane >> 4) & 1) * 16;
    uint32_t aAddr[2];
#pragma unroll
    for (int mt = 0; mt < 2; mt++)
        aAddr[mt] = sAu + (mw * 32 + mt * 16 + l15) * G1_ST2 + kgA;
    const int rB = (lane & 7) + ((lane >> 4) & 1) * 8;
    const int kgB = ((lane >> 3) & 1) * 16;
    uint32_t bAddr[4];
#pragma unroll
    for (int jp = 0; jp < 4; jp++)
        bAddr[jp] = sBu + (nw * 64 + jp * 16 + rB) * G1_ST2 + kgB;

    float acc[2][8][4];
#pragma unroll
    for (int mt = 0; mt < 2; mt++)
#pragma unroll
        for (int j = 0; j < 8; j++)
#pragma unroll
            for (int q = 0; q < 4; q++) acc[mt][j][q] = 0.f;

#pragma unroll
    for (int kk = 0; kk < 8; kk++) {
        const uint32_t ko = kk * 32;
        uint32_t afr[2][4];
#pragma unroll
        for (int mt = 0; mt < 2; mt++)
            ldsm4(afr[mt][0], afr[mt][1], afr[mt][2], afr[mt][3], aAddr[mt] + ko);
        uint32_t bfr[8][2];
#pragma unroll
        for (int jp = 0; jp < 4; jp++)
            ldsm4(bfr[2 * jp][0], bfr[2 * jp][1], bfr[2 * jp + 1][0], bfr[2 * jp + 1][1],
                  bAddr[jp] + ko);
#pragma unroll
        for (int mt = 0; mt < 2; mt++)
#pragma unroll
            for (int j = 0; j < 8; j++) mma16816(acc[mt][j], afr[mt], bfr[j]);
    }

#pragma unroll
    for (int mt = 0; mt < 2; mt++) {
        const int r0 = bm + mw * 32 + mt * 16 + g;
        const int r1 = r0 + 8;
#pragma unroll
        for (int j = 0; j < 8; j++) {
            const int c = nw * 64 + j * 8 + t2;
            __nv_bfloat162 v0 = __floats2bfloat162_rn(acc[mt][j][0], acc[mt][j][1]);
            __nv_bfloat162 v1 = __floats2bfloat162_rn(acc[mt][j][2], acc[mt][j][3]);
            if (r0 < NN) *(uint32_t*)(g_xhb + (size_t)r0 * HC + c) = *(uint32_t*)&v0;
            if (r1 < NN) *(uint32_t*)(g_xhb + (size_t)r1 * HC + c) = *(uint32_t*)&v1;
        }
#pragma unroll
        for (int hh = 0; hh < 2; hh++) {
            float ps0 = 0.f, pd0 = 0.f, ps1 = 0.f, pd1 = 0.f;
#pragma unroll
            for (int jj = 0; jj < 4; jj++) {
                const int j = hh * 4 + jj;
                const int c = nw * 64 + j * 8 + t2;
                float2 s2 = *(const float2*)(att_src + c);
                float2 d2 = *(const float2*)(att_dst + c);
                ps0 = fmaf(acc[mt][j][0], s2.x, fmaf(acc[mt][j][1], s2.y, ps0));
                pd0 = fmaf(acc[mt][j][0], d2.x, fmaf(acc[mt][j][1], d2.y, pd0));
                ps1 = fmaf(acc[mt][j][2], s2.x, fmaf(acc[mt][j][3], s2.y, ps1));
                pd1 = fmaf(acc[mt][j][2], d2.x, fmaf(acc[mt][j][3], d2.y, pd1));
            }
            ps0 += __shfl_xor_sync(0xffffffffu, ps0, 1);
            pd0 += __shfl_xor_sync(0xffffffffu, pd0, 1);
            ps1 += __shfl_xor_sync(0xffffffffu, ps1, 1);
            pd1 += __shfl_xor_sync(0xffffffffu, pd1, 1);
            ps0 += __shfl_xor_sync(0xffffffffu, ps0, 2);
            pd0 += __shfl_xor_sync(0xffffffffu, pd0, 2);
            ps1 += __shfl_xor_sync(0xffffffffu, ps1, 2);
            pd1 += __shfl_xor_sync(0xffffffffu, pd1, 2);
            const int h = nw * 2 + hh;
            if ((lane & 3) == 0) {
                if (r0 < NN) { g_as1[r0 * H1 + h] = ps0; g_ad1[r0 * H1 + h] = pd0; }
                if (r1 < NN) { g_as1[r1 * H1 + h] = ps1; g_ad1[r1 * H1 + h] = pd1; }
            }
        }
    }
}

// ---------------- CSR build (vectorized 4 edges/thread) --------------------------
__global__ void k_hist(const int* __restrict__ ei, int E) {
    int i4 = (blockIdx.x * blockDim.x + threadIdx.x) * 4;
    if (i4 + 4 <= E) {
        int4 d = *(const int4*)(ei + E + i4);
        atomicAdd(&g_deg[d.x], 1);
        atomicAdd(&g_deg[d.y], 1);
        atomicAdd(&g_deg[d.z], 1);
        atomicAdd(&g_deg[d.w], 1);
    } else {
        for (int e = i4; e < E; e++) atomicAdd(&g_deg[ei[E + e]], 1);
    }
}
__global__ void k_scan1() {
    __shared__ int s[256];
    int i = blockIdx.x * 256 + threadIdx.x;
    int v = (i < NN) ? g_deg[i] : 0;
    s[threadIdx.x] = v;
    __syncthreads();
    for (int o = 128; o; o >>= 1) {
        if (threadIdx.x < o) s[threadIdx.x] += s[threadIdx.x + o];
        __syncthreads();
    }
    if (threadIdx.x == 0) g_part[blockIdx.x] = s[0];
}
__global__ void k_scan2() {
    __shared__ int s[256];
    int t = threadIdx.x;
    int v = (t < NBLK) ? g_part[t] : 0;
    s[t] = v;
    __syncthreads();
    for (int o = 1; o < 256; o <<= 1) {
        int u = (t >= o) ? s[t - o] : 0;
        __syncthreads();
        s[t] += u;
        __syncthreads();
    }
    if (t < NBLK) g_part[t] = s[t] - v;
}
__global__ void k_scan3() {
    __shared__ int s[256];
    int t = threadIdx.x;
    int i = blockIdx.x * 256 + t;
    int v = (i < NN) ? g_deg[i] : 0;
    s[t] = v;
    __syncthreads();
    for (int o = 1; o < 256; o <<= 1) {
        int u = (t >= o) ? s[t - o] : 0;
        __syncthreads();
        s[t] += u;
        __syncthreads();
    }
    int base = g_part[blockIdx.x];
    if (i < NN) {
        int off = base + s[t] - v;
        g_off[i] = off;
        g_cur[i] = off;
        if (i == NN - 1) g_off[NN] = base + s[t];
    }
}
__global__ void k_scatter(const int* __restrict__ ei, int E) {
    int i4 = (blockIdx.x * blockDim.x + threadIdx.x) * 4;
    if (i4 + 4 <= E) {
        int4 s = *(const int4*)(ei + i4);
        int4 d = *(const int4*)(ei + E + i4);
        g_ssrc[atomicAdd(&g_cur[d.x], 1)] = s.x;
        g_ssrc[atomicAdd(&g_cur[d.y], 1)] = s.y;
        g_ssrc[atomicAdd(&g_cur[d.z], 1)] = s.z;
        g_ssrc[atomicAdd(&g_cur[d.w], 1)] = s.w;
    } else {
        for (int e = i4; e < E; e++) {
            int dd = ei[E + e];
            g_ssrc[atomicAdd(&g_cur[dd], 1)] = ei[e];
        }
    }
}

// ---------------- layer-1 aggregation: bf16 HFMA2, 2 nodes/warp ------------------
__device__ __forceinline__ void edge_acc1(int s, float ad, int h, int vidx,
                                          const uint4* xb, __nv_bfloat162* acc,
                                          float& wsum) {
    const float a = g_as1[s * H1 + h];
    const uint4 v = xb[(size_t)s * 32 + vidx];
    const float w = exp_lrelu(a + ad);
    wsum += w;
    const __nv_bfloat162 w2 = __float2bfloat162_rn(w);
    const __nv_bfloat162* p = (const __nv_bfloat162*)&v;
#pragma unroll
    for (int j = 0; j < 4; j++) acc[j] = __hfma2(w2, p[j], acc[j]);
}

__global__ void k_agg1(const float* __restrict__ b1) {
    const int warp = threadIdx.x >> 5;
    const int lane = threadIdx.x & 31;
    const int nA = (blockIdx.x * 8 + warp) * 2;
    const int nB = nA + 1;
    const int h = lane >> 2;
    const int q = lane & 3;
    const int vidx = h * 4 + q;
    const uint4* xb = (const uint4*)g_xhb;

    const float adA = g_ad1[nA * H1 + h];
    const float adB = g_ad1[nB * H1 + h];
    __nv_bfloat162 accA[4], accB[4];
    float wsumA, wsumB;
    {   // self loops
        float wA = exp_lrelu(g_as1[nA * H1 + h] + adA);
        float wB = exp_lrelu(g_as1[nB * H1 + h] + adB);
        wsumA = wA; wsumB = wB;
        __nv_bfloat162 wA2 = __float2bfloat162_rn(wA);
        __nv_bfloat162 wB2 = __float2bfloat162_rn(wB);
        uint4 vA = xb[(size_t)nA * 32 + vidx];
        uint4 vB = xb[(size_t)nB * 32 + vidx];
        const __nv_bfloat162* pA = (const __nv_bfloat162*)&vA;
        const __nv_bfloat162* pB = (const __nv_bfloat162*)&vB;
#pragma unroll
        for (int j = 0; j < 4; j++) {
            accA[j] = __hmul2(wA2, pA[j]);
            accB[j] = __hmul2(wB2, pB[j]);
        }
    }

    int eA = g_off[nA];
    const int endA = g_off[nA + 1];
    int eB = endA;
    const int endB = g_off[nB + 1];

    while (eA + 2 <= endA && eB + 2 <= endB) {
        const int sA0 = g_ssrc[eA], sA1 = g_ssrc[eA + 1];
        const int sB0 = g_ssrc[eB], sB1 = g_ssrc[eB + 1];
        edge_acc1(sA0, adA, h, vidx, xb, accA, wsumA);
        edge_acc1(sB0, adB, h, vidx, xb, accB, wsumB);
        edge_acc1(sA1, adA, h, vidx, xb, accA, wsumA);
        edge_acc1(sB1, adB, h, vidx, xb, accB, wsumB);
        eA += 2; eB += 2;
    }
    for (; eA + 2 <= endA; eA += 2) {
        const int s0 = g_ssrc[eA], s1 = g_ssrc[eA + 1];
        edge_acc1(s0, adA, h, vidx, xb, accA, wsumA);
        edge_acc1(s1, adA, h, vidx, xb, accA, wsumA);
    }
    for (; eB + 2 <= endB; eB += 2) {
        const int s0 = g_ssrc[eB], s1 = g_ssrc[eB + 1];
        edge_acc1(s0, adB, h, vidx, xb, accB, wsumB);
        edge_acc1(s1, adB, h, vidx, xb, accB, wsumB);
    }
    if (eA < endA) edge_acc1(g_ssrc[eA], adA, h, vidx, xb, accA, wsumA);
    if (eB < endB) edge_acc1(g_ssrc[eB], adB, h, vidx, xb, accB, wsumB);

    // epilogue
    const int c0 = h * C1 + q * 8;
    float bias[8];
#pragma unroll
    for (int j = 0; j < 8; j++) bias[j] = b1[c0 + j];
    const float invA = 1.0f / wsumA;
    const float invB = 1.0f / wsumB;
    __nv_bfloat162 obA[4], obB[4];
#pragma unroll
    for (int j = 0; j < 4; j++) {
        float2 fA = __bfloat1622float2(accA[j]);
        float2 fB = __bfloat1622float2(accB[j]);
        obA[j] = __floats2bfloat162_rn(elu(fA.x * invA + bias[2 * j]),
                                       elu(fA.y * invA + bias[2 * j + 1]));
        obB[j] = __floats2bfloat162_rn(elu(fB.x * invB + bias[2 * j]),
                                       elu(fB.y * invB + bias[2 * j + 1]));
    }
    ((uint4*)g_h1b)[(size_t)nA * 32 + vidx] = *(uint4*)obA;
    ((uint4*)g_h1b)[(size_t)nB * 32 + vidx] = *(uint4*)obB;
}

// ---------------- GEMM2 HMMA: 128x16x256, fused attention epilogue --------------
#define G2_ST   264
#define G2_ASZ  (128 * G2_ST * 2)
#define G2_BSZ  (16 * G2_ST * 2)
#define G2_SMEM (G2_ASZ + G2_BSZ)
__global__ void __launch_bounds__(256, 2) k_gemm2(const float* __restrict__ W2,
                                                  const float* __restrict__ att_src2,
                                                  const float* __restrict__ att_dst2) {
    extern __shared__ char smem[];
    char* sA = smem;
    char* sB = smem + G2_ASZ;
    const int tid = threadIdx.x;
    const int wid = tid >> 5;
    const int lane = tid & 31;
    const int bm = blockIdx.x * 128;
    const int g = lane >> 2;
    const int t2 = (lane & 3) * 2;

    for (int i = tid; i < G2_BSZ / 4; i += 256) ((uint32_t*)sB)[i] = 0;
#pragma unroll
    for (int i = 0; i < 16; i++) {
        int idx = tid + i * 256;
        int row = idx >> 5;
        int c16 = idx & 31;
        int grow = bm + row;
        uint4 v = make_uint4(0, 0, 0, 0);
        if (grow < NN) v = *(const uint4*)(g_h1b + (size_t)grow * HC + c16 * 8);
        *(uint4*)(sA + row * (G2_ST * 2) + c16 * 16) = v;
    }
    __syncthreads();
    for (int idx = tid; idx < HC * CO; idx += 256) {
        int k = idx / CO;
        int n = idx % CO;
        ((__nv_bfloat16*)sB)[n * G2_ST + k] = __float2bfloat16(W2[idx]);
    }
    __syncthreads();

    float a0c[4] = {0.f, 0.f, 0.f, 0.f};
    float a1c[4] = {0.f, 0.f, 0.f, 0.f};
#pragma unroll
    for (int kk = 0; kk < 16; kk++) {
        const int k0 = kk * 16;
        const int rb = wid * 16;
        uint32_t afr[4];
        afr[0] = *(const uint32_t*)(sA + (rb + g) * (G2_ST * 2) + (k0 + t2) * 2);
        afr[1] = *(const uint32_t*)(sA + (rb + g + 8) * (G2_ST * 2) + (k0 + t2) * 2);
        afr[2] = *(const uint32_t*)(sA + (rb + g) * (G2_ST * 2) + (k0 + 8 + t2) * 2);
        afr[3] = *(const uint32_t*)(sA + (rb + g + 8) * (G2_ST * 2) + (k0 + 8 + t2) * 2);
        uint32_t b0[2], b1[2];
        b0[0] = *(const uint32_t*)(sB + g * (G2_ST * 2) + (k0 + t2) * 2);
        b0[1] = *(const uint32_t*)(sB + g * (G2_ST * 2) + (k0 + 8 + t2) * 2);
        b1[0] = *(const uint32_t*)(sB + (8 + g) * (G2_ST * 2) + (k0 + t2) * 2);
        b1[1] = *(const uint32_t*)(sB + (8 + g) * (G2_ST * 2) + (k0 + 8 + t2) * 2);
        mma16816(a0c, afr, b0);
        mma16816(a1c, afr, b1);
    }

    const int r0 = bm + wid * 16 + g;
    const int r1 = r0 + 8;
    if (r0 < NN) {
        *(float2*)(g_xh2 + (size_t)r0 * 16 + t2) = make_float2(a0c[0], a0c[1]);
        *(float2*)(g_xh2 + (size_t)r0 * 16 + 8 + t2) = make_float2(a1c[0], a1c[1]);
    }
    if (r1 < NN) {
        *(float2*)(g_xh2 + (size_t)r1 * 16 + t2) = make_float2(a0c[2], a0c[3]);
        *(float2*)(g_xh2 + (size_t)r1 * 16 + 8 + t2) = make_float2(a1c[2], a1c[3]);
    }
    float s0x = att_src2[t2], s0y = att_src2[t2 + 1];
    float d0x = att_dst2[t2], d0y = att_dst2[t2 + 1];
    float s1x = 0.f, s1y = 0.f, d1x = 0.f, d1y = 0.f;
    if (t2 == 0) { s1x = att_src2[8]; s1y = att_src2[9]; d1x = att_dst2[8]; d1y = att_dst2[9]; }
    float ps0 = a0c[0] * s0x + a0c[1] * s0y + a1c[0] * s1x + a1c[1] * s1y;
    float pd0 = a0c[0] * d0x + a0c[1] * d0y + a1c[0] * d1x + a1c[1] * d1y;
    float ps1 = a0c[2] * s0x + a0c[3] * s0y + a1c[2] * s1x + a1c[3] * s1y;
    float pd1 = a0c[2] * d0x + a0c[3] * d0y + a1c[2] * d1x + a1c[3] * d1y;
    ps0 += __shfl_xor_sync(0xffffffffu, ps0, 1);
    pd0 += __shfl_xor_sync(0xffffffffu, pd0, 1);
    ps1 += __shfl_xor_sync(0xffffffffu, ps1, 1);
    pd1 += __shfl_xor_sync(0xffffffffu, pd1, 1);
    ps0 += __shfl_xor_sync(0xffffffffu, ps0, 2);
    pd0 += __shfl_xor_sync(0xffffffffu, pd0, 2);
    ps1 += __shfl_xor_sync(0xffffffffu, ps1, 2);
    pd1 += __shfl_xor_sync(0xffffffffu, pd1, 2);
    if ((lane & 3) == 0) {
        if (r0 < NN) { g_as2[r0] = ps0; g_ad2[r0] = pd0; }
        if (r1 < NN) { g_as2[r1] = ps1; g_ad2[r1] = pd1; }
    }
}

// ---------------- layer-2 aggregation ---------------------------------------------
__global__ void k_agg2(const int* __restrict__ batch, const float* __restrict__ b2) {
    int warp = threadIdx.x >> 5;
    int lane = threadIdx.x & 31;
    int n = blockIdx.x * 8 + warp;
    if (n >= NN) return;
    const int half = lane >> 4;
    const int i = lane & 15;
    const float ad = g_ad2[n];
    float wsum = 0.f, acc = 0.f;
    if (half == 0) {
        float w = exp_lrelu(g_as2[n] + ad);
        wsum = w;
        acc = w * g_xh2[(size_t)n * 16 + i];
    }
    const int beg = g_off[n], end = g_off[n + 1];
    for (int e = beg + half; e < end; e += 2) {
        const int s = g_ssrc[e];
        const float we = exp_lrelu(g_as2[s] + ad);
        wsum += we;
        acc = fmaf(we, g_xh2[(size_t)s * 16 + i], acc);
    }
    wsum += __shfl_xor_sync(0xffffffffu, wsum, 16);
    acc += __shfl_xor_sync(0xffffffffu, acc, 16);
    if (half == 0 && i < CO) {
        float out = elu(acc / wsum + b2[i]);
        atomicAdd(&g_sums[batch[n] * CO + i], out);
    }
    if (lane == 0) atomicAdd(&g_cnt[batch[n]], 1.0f);
}

// ---------------- mean + log_softmax ----------------------------------------------
__global__ void k_final(float* __restrict__ out) {
    int g = threadIdx.x;
    if (g >= NG) return;
    float inv = 1.0f / fmaxf(g_cnt[g], 1.0f);
    float v[CO];
    float mx = -1e30f;
#pragma unroll
    for (int c = 0; c < CO; c++) {
        v[c] = g_sums[g * CO + c] * inv;
        mx = fmaxf(mx, v[c]);
    }
    float s = 0.f;
#pragma unroll
    for (int c = 0; c < CO; c++) s += __expf(v[c] - mx);
    float lse = logf(s) + mx;
#pragma unroll
    for (int c = 0; c < CO; c++) out[g * CO + c] = v[c] - lse;
}

// ---------------- launcher ----------------------------------------------------------
extern "C" void kernel_launch(void* const* d_in, const int* in_sizes, int n_in,
                              void* d_out, int out_size) {
    const float* x        = (const float*)d_in[0];
    const int*   ei       = (const int*)d_in[1];
    const int*   batch    = (const int*)d_in[2];
    const float* W1       = (const float*)d_in[3];
    const float* att_src1 = (const float*)d_in[4];
    const float* att_dst1 = (const float*)d_in[5];
    const float* b1       = (const float*)d_in[6];
    const float* W2       = (const float*)d_in[7];
    const float* att_src2 = (const float*)d_in[8];
    const float* att_dst2 = (const float*)d_in[9];
    const float* b2       = (const float*)d_in[10];
    float* out = (float*)d_out;
    const int E = in_sizes[1] / 2;
    const int E4blk = ((E + 3) / 4 + 255) / 256;

    static cudaStream_t s1 = nullptr;
    static cudaEvent_t e0 = nullptr, e1 = nullptr;
    if (!s1) {
        cudaStreamCreateWithFlags(&s1, cudaStreamNonBlocking);
        cudaEventCreateWithFlags(&e0, cudaEventDisableTiming);
        cudaEventCreateWithFlags(&e1, cudaEventDisableTiming);
        cudaFuncSetAttribute(k_gemm1, cudaFuncAttributeMaxDynamicSharedMemorySize, G1_SMEM);
        cudaFuncSetAttribute(k_gemm2, cudaFuncAttributeMaxDynamicSharedMemorySize, G2_SMEM);
    }

    cudaEventRecord(e0, 0);
    k_zero<<<(NN + 255) / 256, 256>>>();
    k_hist<<<E4blk, 256>>>(ei, E);
    cudaStreamWaitEvent(s1, e0, 0);
    k_cvt_w<<<dim3(FIN / 32, HC / 32), dim3(32, 32), 0, s1>>>(W1);
    k_gemm1<<<(NN + 63) / 64, 256, G1_SMEM, s1>>>(x, att_src1, att_dst1);
    cudaEventRecord(e1, s1);
    k_scan1<<<NBLK, 256>>>();
    k_scan2<<<1, 256>>>();
    k_scan3<<<NBLK, 256>>>();
    k_scatter<<<E4blk, 256>>>(ei, E);
    cudaStreamWaitEvent(0, e1, 0);
    k_agg1<<<NN / 16, 256>>>(b1);
    k_gemm2<<<(NN + 127) / 128, 256, G2_SMEM>>>(W2, att_src2, att_dst2);
    k_agg2<<<(NN + 7) / 8, 256>>>(batch, b2);
    k_final<<<1, NG>>>(out);
}

// round 16
// speedup vs baseline: 1.0709x; 1.0397x over previous
#include <cuda_runtime.h>
#include <cuda_bf16.h>
#include <cstdint>

#define NN   50000
#define EE   800000
#define FIN  128
#define H1   8
#define C1   32
#define HC   256
#define CO   10
#define NG   128
#define NEG_SLOPE 0.2f
#define NBLK 196          // ceil(NN/256)

// ---------------- scratch ----------------------------------------------------
__device__ __nv_bfloat16  g_xhb[(size_t)NN * HC];
__device__ __nv_bfloat16  g_h1b[(size_t)NN * HC];
__device__ __nv_bfloat16  g_w1b[(size_t)HC * FIN];
__device__ float g_as1[NN * H1];
__device__ float g_ad1[NN * H1];
__device__ int   g_deg[NN];
__device__ int   g_off[NN + 1];
__device__ int   g_cur[NN];
__device__ int   g_part[NBLK];
__device__ int   g_ssrc[EE];
__device__ __nv_bfloat16 g_xh2b[(size_t)NN * 16];   // layer2 pre-act (bf16, stride 16)
__device__ float g_as2[NN];
__device__ float g_ad2[NN];
__device__ float g_sums[NG * CO];
__device__ float g_cnt[NG];

__device__ __forceinline__ float elu(float x) {
    return x > 0.0f ? x : (__expf(x) - 1.0f);
}
// exp(leaky_relu(x, 0.2)) = 2^(0.6*log2e*x + 0.4*log2e*|x|)
__device__ __forceinline__ float exp_lrelu(float x) {
    float t = fmaf(0.57707802f, fabsf(x), 0.86561702f * x);
    float w;
    asm("ex2.approx.f32 %0, %1;" : "=f"(w) : "f"(t));
    return w;
}
__device__ __forceinline__ void mma16816(float* d, const uint32_t* a, const uint32_t* b) {
    asm volatile(
        "mma.sync.aligned.m16n8k16.row.col.f32.bf16.bf16.f32 "
        "{%0,%1,%2,%3}, {%4,%5,%6,%7}, {%8,%9}, {%0,%1,%2,%3};"
        : "+f"(d[0]), "+f"(d[1]), "+f"(d[2]), "+f"(d[3])
        : "r"(a[0]), "r"(a[1]), "r"(a[2]), "r"(a[3]), "r"(b[0]), "r"(b[1]));
}
__device__ __forceinline__ void ldsm4(uint32_t& r0, uint32_t& r1, uint32_t& r2,
                                      uint32_t& r3, uint32_t addr) {
    asm volatile("ldmatrix.sync.aligned.m8n8.x4.shared.b16 {%0,%1,%2,%3}, [%4];"
                 : "=r"(r0), "=r"(r1), "=r"(r2), "=r"(r3) : "r"(addr));
}

// ---------------- 0. zero -----------------------------------------------------
__global__ void k_zero() {
    int i = blockIdx.x * blockDim.x + threadIdx.x;
    if (i < NN) g_deg[i] = 0;
    if (i < NG * CO) g_sums[i] = 0.0f;
    if (i < NG) g_cnt[i] = 0.0f;
}

// ---------------- W1 transpose+convert ----------------------------------------
__global__ void k_cvt_w(const float* __restrict__ W1) {
    __shared__ float s[32][33];
    int k0 = blockIdx.x * 32;
    int n0 = blockIdx.y * 32;
    int tx = threadIdx.x, ty = threadIdx.y;
    s[ty][tx] = W1[(size_t)(k0 + ty) * HC + n0 + tx];
    __syncthreads();
    g_w1b[(size_t)(n0 + ty) * FIN + k0 + tx] = __float2bfloat16(s[tx][ty]);
}

// ---------------- GEMM1 HMMA persistent: B resident, A per M-tile ---------------
#define G1_ST    136
#define G1_ST2   (G1_ST * 2)
#define G1_BSZ   (256 * G1_ST2)      // 69632
#define G1_ASZ   (64 * G1_ST2)       // 17408
#define G1_SMEM  (G1_BSZ + G1_ASZ)   // 87040
#define G1_CTAS  296
__global__ void __launch_bounds__(256, 2) k_gemm1(const float* __restrict__ x,
                                                  const float* __restrict__ att_src,
                                                  const float* __restrict__ att_dst) {
    extern __shared__ char smem[];
    char* sB = smem;
    char* sA = smem + G1_BSZ;
    const int tid = threadIdx.x;
    const int wid = tid >> 5;
    const int lane = tid & 31;
    const int mw = wid >> 2;
    const int nw = wid & 3;
    const int g = lane >> 2;
    const int t2 = (lane & 3) * 2;

    // ---- load B once (W1 bf16, 256x128, padded stride) ----
#pragma unroll
    for (int i = 0; i < 16; i++) {
        int idx = tid + i * 256;
        int row = idx >> 4;
        int c16 = idx & 15;
        uint4 v = *(const uint4*)(g_w1b + (size_t)row * FIN + c16 * 8);
        *(uint4*)(sB + row * G1_ST2 + c16 * 16) = v;
    }

    // ---- ldmatrix addressing (fixed, hoisted) ----
    const uint32_t sAu = (uint32_t)__cvta_generic_to_shared(sA);
    const uint32_t sBu = (uint32_t)__cvta_generic_to_shared(sB);
    const int l15 = lane & 15;
    const int kgA = ((lane >> 4) & 1) * 16;
    uint32_t aAddr[2];
#pragma unroll
    for (int mt = 0; mt < 2; mt++)
        aAddr[mt] = sAu + (mw * 32 + mt * 16 + l15) * G1_ST2 + kgA;
    const int rB = (lane & 7) + ((lane >> 4) & 1) * 8;
    const int kgB = ((lane >> 3) & 1) * 16;
    uint32_t bAddr[4];
#pragma unroll
    for (int jp = 0; jp < 4; jp++)
        bAddr[jp] = sBu + (nw * 64 + jp * 16 + rB) * G1_ST2 + kgB;

    // ---- persistent loop over M tiles ----
    for (int tile = blockIdx.x; tile * 64 < NN; tile += G1_CTAS) {
        const int bm = tile * 64;
        // load A tile (64 rows of x, fp32 -> bf16)
#pragma unroll
        for (int i = 0; i < 8; i++) {
            int idx = tid + i * 256;
            int row = idx >> 5;
            int c4 = idx & 31;
            float4 v = make_float4(0.f, 0.f, 0.f, 0.f);
            int grow = bm + row;
            if (grow < NN) v = *(const float4*)(x + (size_t)grow * FIN + c4 * 4);
            __nv_bfloat162 b0 = __floats2bfloat162_rn(v.x, v.y);
            __nv_bfloat162 b1 = __floats2bfloat162_rn(v.z, v.w);
            uint2 p = make_uint2(*(uint32_t*)&b0, *(uint32_t*)&b1);
            *(uint2*)(sA + row * G1_ST2 + c4 * 8) = p;
        }
        __syncthreads();

        float acc[2][8][4];
#pragma unroll
        for (int mt = 0; mt < 2; mt++)
#pragma unroll
            for (int j = 0; j < 8; j++)
#pragma unroll
                for (int q = 0; q < 4; q++) acc[mt][j][q] = 0.f;

#pragma unroll
        for (int kk = 0; kk < 8; kk++) {
            const uint32_t ko = kk * 32;
            uint32_t afr[2][4];
#pragma unroll
            for (int mt = 0; mt < 2; mt++)
                ldsm4(afr[mt][0], afr[mt][1], afr[mt][2], afr[mt][3], aAddr[mt] + ko);
            uint32_t bfr[8][2];
#pragma unroll
            for (int jp = 0; jp < 4; jp++)
                ldsm4(bfr[2 * jp][0], bfr[2 * jp][1], bfr[2 * jp + 1][0], bfr[2 * jp + 1][1],
                      bAddr[jp] + ko);
#pragma unroll
            for (int mt = 0; mt < 2; mt++)
#pragma unroll
                for (int j = 0; j < 8; j++) mma16816(acc[mt][j], afr[mt], bfr[j]);
        }

        // ---- epilogue ----
#pragma unroll
        for (int mt = 0; mt < 2; mt++) {
            const int r0 = bm + mw * 32 + mt * 16 + g;
            const int r1 = r0 + 8;
#pragma unroll
            for (int j = 0; j < 8; j++) {
                const int c = nw * 64 + j * 8 + t2;
                __nv_bfloat162 v0 = __floats2bfloat162_rn(acc[mt][j][0], acc[mt][j][1]);
                __nv_bfloat162 v1 = __floats2bfloat162_rn(acc[mt][j][2], acc[mt][j][3]);
                if (r0 < NN) *(uint32_t*)(g_xhb + (size_t)r0 * HC + c) = *(uint32_t*)&v0;
                if (r1 < NN) *(uint32_t*)(g_xhb + (size_t)r1 * HC + c) = *(uint32_t*)&v1;
            }
#pragma unroll
            for (int hh = 0; hh < 2; hh++) {
                float ps0 = 0.f, pd0 = 0.f, ps1 = 0.f, pd1 = 0.f;
#pragma unroll
                for (int jj = 0; jj < 4; jj++) {
                    const int j = hh * 4 + jj;
                    const int c = nw * 64 + j * 8 + t2;
                    float2 s2 = *(const float2*)(att_src + c);
                    float2 d2 = *(const float2*)(att_dst + c);
                    ps0 = fmaf(acc[mt][j][0], s2.x, fmaf(acc[mt][j][1], s2.y, ps0));
                    pd0 = fmaf(acc[mt][j][0], d2.x, fmaf(acc[mt][j][1], d2.y, pd0));
                    ps1 = fmaf(acc[mt][j][2], s2.x, fmaf(acc[mt][j][3], s2.y, ps1));
                    pd1 = fmaf(acc[mt][j][2], d2.x, fmaf(acc[mt][j][3], d2.y, pd1));
                }
                ps0 += __shfl_xor_sync(0xffffffffu, ps0, 1);
                pd0 += __shfl_xor_sync(0xffffffffu, pd0, 1);
                ps1 += __shfl_xor_sync(0xffffffffu, ps1, 1);
                pd1 += __shfl_xor_sync(0xffffffffu, pd1, 1);
                ps0 += __shfl_xor_sync(0xffffffffu, ps0, 2);
                pd0 += __shfl_xor_sync(0xffffffffu, pd0, 2);
                ps1 += __shfl_xor_sync(0xffffffffu, ps1, 2);
                pd1 += __shfl_xor_sync(0xffffffffu, pd1, 2);
                const int h = nw * 2 + hh;
                if ((lane & 3) == 0) {
                    if (r0 < NN) { g_as1[r0 * H1 + h] = ps0; g_ad1[r0 * H1 + h] = pd0; }
                    if (r1 < NN) { g_as1[r1 * H1 + h] = ps1; g_ad1[r1 * H1 + h] = pd1; }
                }
            }
        }
        __syncthreads();   // before next iteration overwrites sA
    }
}

// ---------------- CSR build (vectorized 4 edges/thread) --------------------------
__global__ void k_hist(const int* __restrict__ ei, int E) {
    int i4 = (blockIdx.x * blockDim.x + threadIdx.x) * 4;
    if (i4 + 4 <= E) {
        int4 d = *(const int4*)(ei + E + i4);
        atomicAdd(&g_deg[d.x], 1);
        atomicAdd(&g_deg[d.y], 1);
        atomicAdd(&g_deg[d.z], 1);
        atomicAdd(&g_deg[d.w], 1);
    } else {
        for (int e = i4; e < E; e++) atomicAdd(&g_deg[ei[E + e]], 1);
    }
}
__global__ void k_scan1() {
    __shared__ int s[256];
    int i = blockIdx.x * 256 + threadIdx.x;
    int v = (i < NN) ? g_deg[i] : 0;
    s[threadIdx.x] = v;
    __syncthreads();
    for (int o = 128; o; o >>= 1) {
        if (threadIdx.x < o) s[threadIdx.x] += s[threadIdx.x + o];
        __syncthreads();
    }
    if (threadIdx.x == 0) g_part[blockIdx.x] = s[0];
}
__global__ void k_scan2() {
    __shared__ int s[256];
    int t = threadIdx.x;
    int v = (t < NBLK) ? g_part[t] : 0;
    s[t] = v;
    __syncthreads();
    for (int o = 1; o < 256; o <<= 1) {
        int u = (t >= o) ? s[t - o] : 0;
        __syncthreads();
        s[t] += u;
        __syncthreads();
    }
    if (t < NBLK) g_part[t] = s[t] - v;
}
__global__ void k_scan3() {
    __shared__ int s[256];
    int t = threadIdx.x;
    int i = blockIdx.x * 256 + t;
    int v = (i < NN) ? g_deg[i] : 0;
    s[t] = v;
    __syncthreads();
    for (int o = 1; o < 256; o <<= 1) {
        int u = (t >= o) ? s[t - o] : 0;
        __syncthreads();
        s[t] += u;
        __syncthreads();
    }
    int base = g_part[blockIdx.x];
    if (i < NN) {
        int off = base + s[t] - v;
        g_off[i] = off;
        g_cur[i] = off;
        if (i == NN - 1) g_off[NN] = base + s[t];
    }
}
__global__ void k_scatter(const int* __restrict__ ei, int E) {
    int i4 = (blockIdx.x * blockDim.x + threadIdx.x) * 4;
    if (i4 + 4 <= E) {
        int4 s = *(const int4*)(ei + i4);
        int4 d = *(const int4*)(ei + E + i4);
        g_ssrc[atomicAdd(&g_cur[d.x], 1)] = s.x;
        g_ssrc[atomicAdd(&g_cur[d.y], 1)] = s.y;
        g_ssrc[atomicAdd(&g_cur[d.z], 1)] = s.z;
        g_ssrc[atomicAdd(&g_cur[d.w], 1)] = s.w;
    } else {
        for (int e = i4; e < E; e++) {
            int dd = ei[E + e];
            g_ssrc[atomicAdd(&g_cur[dd], 1)] = ei[e];
        }
    }
}

// ---------------- layer-1 aggregation: bf16 HFMA2, 2 nodes/warp ------------------
__device__ __forceinline__ void edge_acc1(int s, float ad, int h, int vidx,
                                          const uint4* xb, __nv_bfloat162* acc,
                                          float& wsum) {
    const float a = g_as1[s * H1 + h];
    const uint4 v = xb[(size_t)s * 32 + vidx];
    const float w = exp_lrelu(a + ad);
    wsum += w;
    const __nv_bfloat162 w2 = __float2bfloat162_rn(w);
    const __nv_bfloat162* p = (const __nv_bfloat162*)&v;
#pragma unroll
    for (int j = 0; j < 4; j++) acc[j] = __hfma2(w2, p[j], acc[j]);
}

__global__ void k_agg1(const float* __restrict__ b1) {
    const int warp = threadIdx.x >> 5;
    const int lane = threadIdx.x & 31;
    const int nA = (blockIdx.x * 8 + warp) * 2;
    const int nB = nA + 1;
    const int h = lane >> 2;
    const int q = lane & 3;
    const int vidx = h * 4 + q;
    const uint4* xb = (const uint4*)g_xhb;

    const float adA = g_ad1[nA * H1 + h];
    const float adB = g_ad1[nB * H1 + h];
    __nv_bfloat162 accA[4], accB[4];
    float wsumA, wsumB;
    {
        float wA = exp_lrelu(g_as1[nA * H1 + h] + adA);
        float wB = exp_lrelu(g_as1[nB * H1 + h] + adB);
        wsumA = wA; wsumB = wB;
        __nv_bfloat162 wA2 = __float2bfloat162_rn(wA);
        __nv_bfloat162 wB2 = __float2bfloat162_rn(wB);
        uint4 vA = xb[(size_t)nA * 32 + vidx];
        uint4 vB = xb[(size_t)nB * 32 + vidx];
        const __nv_bfloat162* pA = (const __nv_bfloat162*)&vA;
        const __nv_bfloat162* pB = (const __nv_bfloat162*)&vB;
#pragma unroll
        for (int j = 0; j < 4; j++) {
            accA[j] = __hmul2(wA2, pA[j]);
            accB[j] = __hmul2(wB2, pB[j]);
        }
    }

    int eA = g_off[nA];
    const int endA = g_off[nA + 1];
    int eB = endA;
    const int endB = g_off[nB + 1];

    while (eA + 2 <= endA && eB + 2 <= endB) {
        const int sA0 = g_ssrc[eA], sA1 = g_ssrc[eA + 1];
        const int sB0 = g_ssrc[eB], sB1 = g_ssrc[eB + 1];
        edge_acc1(sA0, adA, h, vidx, xb, accA, wsumA);
        edge_acc1(sB0, adB, h, vidx, xb, accB, wsumB);
        edge_acc1(sA1, adA, h, vidx, xb, accA, wsumA);
        edge_acc1(sB1, adB, h, vidx, xb, accB, wsumB);
        eA += 2; eB += 2;
    }
    for (; eA + 2 <= endA; eA += 2) {
        const int s0 = g_ssrc[eA], s1 = g_ssrc[eA + 1];
        edge_acc1(s0, adA, h, vidx, xb, accA, wsumA);
        edge_acc1(s1, adA, h, vidx, xb, accA, wsumA);
    }
    for (; eB + 2 <= endB; eB += 2) {
        const int s0 = g_ssrc[eB], s1 = g_ssrc[eB + 1];
        edge_acc1(s0, adB, h, vidx, xb, accB, wsumB);
        edge_acc1(s1, adB, h, vidx, xb, accB, wsumB);
    }
    if (eA < endA) edge_acc1(g_ssrc[eA], adA, h, vidx, xb, accA, wsumA);
    if (eB < endB) edge_acc1(g_ssrc[eB], adB, h, vidx, xb, accB, wsumB);

    const int c0 = h * C1 + q * 8;
    float bias[8];
#pragma unroll
    for (int j = 0; j < 8; j++) bias[j] = b1[c0 + j];
    const float invA = 1.0f / wsumA;
    const float invB = 1.0f / wsumB;
    __nv_bfloat162 obA[4], obB[4];
#pragma unroll
    for (int j = 0; j < 4; j++) {
        float2 fA = __bfloat1622float2(accA[j]);
        float2 fB = __bfloat1622float2(accB[j]);
        obA[j] = __floats2bfloat162_rn(elu(fA.x * invA + bias[2 * j]),
                                       elu(fA.y * invA + bias[2 * j + 1]));
        obB[j] = __floats2bfloat162_rn(elu(fB.x * invB + bias[2 * j]),
                                       elu(fB.y * invB + bias[2 * j + 1]));
    }
    ((uint4*)g_h1b)[(size_t)nA * 32 + vidx] = *(uint4*)obA;
    ((uint4*)g_h1b)[(size_t)nB * 32 + vidx] = *(uint4*)obB;
}

// ---------------- GEMM2 HMMA: 128x16x256, fused attention epilogue --------------
#define G2_ST   264
#define G2_ASZ  (128 * G2_ST * 2)
#define G2_BSZ  (16 * G2_ST * 2)
#define G2_SMEM (G2_ASZ + G2_BSZ)
__global__ void __launch_bounds__(256, 2) k_gemm2(const float* __restrict__ W2,
                                                  const float* __restrict__ att_src2,
                                                  const float* __restrict__ att_dst2) {
    extern __shared__ char smem[];
    char* sA = smem;
    char* sB = smem + G2_ASZ;
    const int tid = threadIdx.x;
    const int wid = tid >> 5;
    const int lane = tid & 31;
    const int bm = blockIdx.x * 128;
    const int g = lane >> 2;
    const int t2 = (lane & 3) * 2;

    for (int i = tid; i < G2_BSZ / 4; i += 256) ((uint32_t*)sB)[i] = 0;
#pragma unroll
    for (int i = 0; i < 16; i++) {
        int idx = tid + i * 256;
        int row = idx >> 5;
        int c16 = idx & 31;
        int grow = bm + row;
        uint4 v = make_uint4(0, 0, 0, 0);
        if (grow < NN) v = *(const uint4*)(g_h1b + (size_t)grow * HC + c16 * 8);
        *(uint4*)(sA + row * (G2_ST * 2) + c16 * 16) = v;
    }
    __syncthreads();
    for (int idx = tid; idx < HC * CO; idx += 256) {
        int k = idx / CO;
        int n = idx % CO;
        ((__nv_bfloat16*)sB)[n * G2_ST + k] = __float2bfloat16(W2[idx]);
    }
    __syncthreads();

    float a0c[4] = {0.f, 0.f, 0.f, 0.f};
    float a1c[4] = {0.f, 0.f, 0.f, 0.f};
#pragma unroll
    for (int kk = 0; kk < 16; kk++) {
        const int k0 = kk * 16;
        const int rb = wid * 16;
        uint32_t afr[4];
        afr[0] = *(const uint32_t*)(sA + (rb + g) * (G2_ST * 2) + (k0 + t2) * 2);
        afr[1] = *(const uint32_t*)(sA + (rb + g + 8) * (G2_ST * 2) + (k0 + t2) * 2);
        afr[2] = *(const uint32_t*)(sA + (rb + g) * (G2_ST * 2) + (k0 + 8 + t2) * 2);
        afr[3] = *(const uint32_t*)(sA + (rb + g + 8) * (G2_ST * 2) + (k0 + 8 + t2) * 2);
        uint32_t b0[2], b1[2];
        b0[0] = *(const uint32_t*)(sB + g * (G2_ST * 2) + (k0 + t2) * 2);
        b0[1] = *(const uint32_t*)(sB + g * (G2_ST * 2) + (k0 + 8 + t2) * 2);
        b1[0] = *(const uint32_t*)(sB + (8 + g) * (G2_ST * 2) + (k0 + t2) * 2);
        b1[1] = *(const uint32_t*)(sB + (8 + g) * (G2_ST * 2) + (k0 + 8 + t2) * 2);
        mma16816(a0c, afr, b0);
        mma16816(a1c, afr, b1);
    }

    const int r0 = bm + wid * 16 + g;
    const int r1 = r0 + 8;
    if (r0 < NN) {
        __nv_bfloat162 p0 = __floats2bfloat162_rn(a0c[0], a0c[1]);
        __nv_bfloat162 p1 = __floats2bfloat162_rn(a1c[0], a1c[1]);
        *(uint32_t*)(g_xh2b + (size_t)r0 * 16 + t2) = *(uint32_t*)&p0;
        *(uint32_t*)(g_xh2b + (size_t)r0 * 16 + 8 + t2) = *(uint32_t*)&p1;
    }
    if (r1 < NN) {
        __nv_bfloat162 p0 = __floats2bfloat162_rn(a0c[2], a0c[3]);
        __nv_bfloat162 p1 = __floats2bfloat162_rn(a1c[2], a1c[3]);
        *(uint32_t*)(g_xh2b + (size_t)r1 * 16 + t2) = *(uint32_t*)&p0;
        *(uint32_t*)(g_xh2b + (size_t)r1 * 16 + 8 + t2) = *(uint32_t*)&p1;
    }
    float s0x = att_src2[t2], s0y = att_src2[t2 + 1];
    float d0x = att_dst2[t2], d0y = att_dst2[t2 + 1];
    float s1x = 0.f, s1y = 0.f, d1x = 0.f, d1y = 0.f;
    if (t2 == 0) { s1x = att_src2[8]; s1y = att_src2[9]; d1x = att_dst2[8]; d1y = att_dst2[9]; }
    float ps0 = a0c[0] * s0x + a0c[1] * s0y + a1c[0] * s1x + a1c[1] * s1y;
    float pd0 = a0c[0] * d0x + a0c[1] * d0y + a1c[0] * d1x + a1c[1] * d1y;
    float ps1 = a0c[2] * s0x + a0c[3] * s0y + a1c[2] * s1x + a1c[3] * s1y;
    float pd1 = a0c[2] * d0x + a0c[3] * d0y + a1c[2] * d1x + a1c[3] * d1y;
    ps0 += __shfl_xor_sync(0xffffffffu, ps0, 1);
    pd0 += __shfl_xor_sync(0xffffffffu, pd0, 1);
    ps1 += __shfl_xor_sync(0xffffffffu, ps1, 1);
    pd1 += __shfl_xor_sync(0xffffffffu, pd1, 1);
    ps0 += __shfl_xor_sync(0xffffffffu, ps0, 2);
    pd0 += __shfl_xor_sync(0xffffffffu, pd0, 2);
    ps1 += __shfl_xor_sync(0xffffffffu, ps1, 2);
    pd1 += __shfl_xor_sync(0xffffffffu, pd1, 2);
    if ((lane & 3) == 0) {
        if (r0 < NN) { g_as2[r0] = ps0; g_ad2[r0] = pd0; }
        if (r1 < NN) { g_as2[r1] = ps1; g_ad2[r1] = pd1; }
    }
}

// ---------------- layer-2 aggregation (bf16 payload) ------------------------------
__global__ void k_agg2(const int* __restrict__ batch, const float* __restrict__ b2) {
    int warp = threadIdx.x >> 5;
    int lane = threadIdx.x & 31;
    int n = blockIdx.x * 8 + warp;
    if (n >= NN) return;
    const int half = lane >> 4;
    const int i = lane & 15;
    const float ad = g_ad2[n];
    float wsum = 0.f, acc = 0.f;
    if (half == 0) {
        float w = exp_lrelu(g_as2[n] + ad);
        wsum = w;
        acc = w * __bfloat162float(g_xh2b[(size_t)n * 16 + i]);
    }
    const int beg = g_off[n], end = g_off[n + 1];
    for (int e = beg + half; e < end; e += 2) {
        const int s = g_ssrc[e];
        const float we = exp_lrelu(g_as2[s] + ad);
        wsum += we;
        acc = fmaf(we, __bfloat162float(g_xh2b[(size_t)s * 16 + i]), acc);
    }
    wsum += __shfl_xor_sync(0xffffffffu, wsum, 16);
    acc += __shfl_xor_sync(0xffffffffu, acc, 16);
    if (half == 0 && i < CO) {
        float out = elu(acc / wsum + b2[i]);
        atomicAdd(&g_sums[batch[n] * CO + i], out);
    }
    if (lane == 0) atomicAdd(&g_cnt[batch[n]], 1.0f);
}

// ---------------- mean + log_softmax ----------------------------------------------
__global__ void k_final(float* __restrict__ out) {
    int g = threadIdx.x;
    if (g >= NG) return;
    float inv = 1.0f / fmaxf(g_cnt[g], 1.0f);
    float v[CO];
    float mx = -1e30f;
#pragma unroll
    for (int c = 0; c < CO; c++) {
        v[c] = g_sums[g * CO + c] * inv;
        mx = fmaxf(mx, v[c]);
    }
    float s = 0.f;
#pragma unroll
    for (int c = 0; c < CO; c++) s += __expf(v[c] - mx);
    float lse = logf(s) + mx;
#pragma unroll
    for (int c = 0; c < CO; c++) out[g * CO + c] = v[c] - lse;
}

// ---------------- launcher ----------------------------------------------------------
extern "C" void kernel_launch(void* const* d_in, const int* in_sizes, int n_in,
                              void* d_out, int out_size) {
    const float* x        = (const float*)d_in[0];
    const int*   ei       = (const int*)d_in[1];
    const int*   batch    = (const int*)d_in[2];
    const float* W1       = (const float*)d_in[3];
    const float* att_src1 = (const float*)d_in[4];
    const float* att_dst1 = (const float*)d_in[5];
    const float* b1       = (const float*)d_in[6];
    const float* W2       = (const float*)d_in[7];
    const float* att_src2 = (const float*)d_in[8];
    const float* att_dst2 = (const float*)d_in[9];
    const float* b2       = (const float*)d_in[10];
    float* out = (float*)d_out;
    const int E = in_sizes[1] / 2;
    const int E4blk = ((E + 3) / 4 + 255) / 256;

    static cudaStream_t s1 = nullptr;
    static cudaEvent_t e0 = nullptr, e1 = nullptr;
    if (!s1) {
        cudaStreamCreateWithFlags(&s1, cudaStreamNonBlocking);
        cudaEventCreateWithFlags(&e0, cudaEventDisableTiming);
        cudaEventCreateWithFlags(&e1, cudaEventDisableTiming);
        cudaFuncSetAttribute(k_gemm1, cudaFuncAttributeMaxDynamicSharedMemorySize, G1_SMEM);
        cudaFuncSetAttribute(k_gemm2, cudaFuncAttributeMaxDynamicSharedMemorySize, G2_SMEM);
    }

    cudaEventRecord(e0, 0);
    k_zero<<<(NN + 255) / 256, 256>>>();
    k_hist<<<E4blk, 256>>>(ei, E);
    cudaStreamWaitEvent(s1, e0, 0);
    k_cvt_w<<<dim3(FIN / 32, HC / 32), dim3(32, 32), 0, s1>>>(W1);
    k_gemm1<<<G1_CTAS, 256, G1_SMEM, s1>>>(x, att_src1, att_dst1);
    cudaEventRecord(e1, s1);
    k_scan1<<<NBLK, 256>>>();
    k_scan2<<<1, 256>>>();
    k_scan3<<<NBLK, 256>>>();
    k_scatter<<<E4blk, 256>>>(ei, E);
    cudaStreamWaitEvent(0, e1, 0);
    k_agg1<<<NN / 16, 256>>>(b1);
    k_gemm2<<<(NN + 127) / 128, 256, G2_SMEM>>>(W2, att_src2, att_dst2);
    k_agg2<<<(NN + 7) / 8, 256>>>(batch, b2);
    k_final<<<1, NG>>>(out);
}

// round 17
// speedup vs baseline: 1.0978x; 1.0251x over previous
#include <cuda_runtime.h>
#include <cuda_bf16.h>
#include <cstdint>

#define NN   50000
#define EE   800000
#define FIN  128
#define H1   8
#define C1   32
#define HC   256
#define CO   10
#define NG   128
#define NEG_SLOPE 0.2f
#define NBLK 196          // ceil(NN/256)

// ---------------- scratch ----------------------------------------------------
__device__ __nv_bfloat16  g_xhb[(size_t)NN * HC];
__device__ __nv_bfloat16  g_w1b[(size_t)HC * FIN];
__device__ float g_as1[NN * H1];
__device__ float g_ad1[NN * H1];
__device__ int   g_deg[NN];
__device__ int   g_off[NN + 1];
__device__ int   g_cur[NN];
__device__ int   g_part[NBLK];
__device__ int   g_ssrc[EE];
__device__ __nv_bfloat16 g_xh2b[(size_t)NN * 16];
__device__ float g_as2[NN];
__device__ float g_ad2[NN];
__device__ float g_sums[NG * CO];
__device__ float g_cnt[NG];

__device__ __forceinline__ float elu(float x) {
    return x > 0.0f ? x : (__expf(x) - 1.0f);
}
__device__ __forceinline__ float exp_lrelu(float x) {
    float t = fmaf(0.57707802f, fabsf(x), 0.86561702f * x);
    float w;
    asm("ex2.approx.f32 %0, %1;" : "=f"(w) : "f"(t));
    return w;
}
__device__ __forceinline__ void mma16816(float* d, const uint32_t* a, const uint32_t* b) {
    asm volatile(
        "mma.sync.aligned.m16n8k16.row.col.f32.bf16.bf16.f32 "
        "{%0,%1,%2,%3}, {%4,%5,%6,%7}, {%8,%9}, {%0,%1,%2,%3};"
        : "+f"(d[0]), "+f"(d[1]), "+f"(d[2]), "+f"(d[3])
        : "r"(a[0]), "r"(a[1]), "r"(a[2]), "r"(a[3]), "r"(b[0]), "r"(b[1]));
}
__device__ __forceinline__ void ldsm4(uint32_t& r0, uint32_t& r1, uint32_t& r2,
                                      uint32_t& r3, uint32_t addr) {
    asm volatile("ldmatrix.sync.aligned.m8n8.x4.shared.b16 {%0,%1,%2,%3}, [%4];"
                 : "=r"(r0), "=r"(r1), "=r"(r2), "=r"(r3) : "r"(addr));
}

// ---------------- 0. zero -----------------------------------------------------
__global__ void k_zero() {
    int i = blockIdx.x * blockDim.x + threadIdx.x;
    if (i < NN) g_deg[i] = 0;
    if (i < NG * CO) g_sums[i] = 0.0f;
    if (i < NG) g_cnt[i] = 0.0f;
}

// ---------------- W1 transpose+convert ----------------------------------------
__global__ void k_cvt_w(const float* __restrict__ W1) {
    __shared__ float s[32][33];
    int k0 = blockIdx.x * 32;
    int n0 = blockIdx.y * 32;
    int tx = threadIdx.x, ty = threadIdx.y;
    s[ty][tx] = W1[(size_t)(k0 + ty) * HC + n0 + tx];
    __syncthreads();
    g_w1b[(size_t)(n0 + ty) * FIN + k0 + tx] = __float2bfloat16(s[tx][ty]);
}

// ---------------- GEMM1 HMMA persistent: B resident, A per M-tile ---------------
#define G1_ST    136
#define G1_ST2   (G1_ST * 2)
#define G1_BSZ   (256 * G1_ST2)
#define G1_ASZ   (64 * G1_ST2)
#define G1_SMEM  (G1_BSZ + G1_ASZ)
#define G1_CTAS  296
__global__ void __launch_bounds__(256, 2) k_gemm1(const float* __restrict__ x,
                                                  const float* __restrict__ att_src,
                                                  const float* __restrict__ att_dst) {
    extern __shared__ char smem[];
    char* sB = smem;
    char* sA = smem + G1_BSZ;
    const int tid = threadIdx.x;
    const int wid = tid >> 5;
    const int lane = tid & 31;
    const int mw = wid >> 2;
    const int nw = wid & 3;
    const int g = lane >> 2;
    const int t2 = (lane & 3) * 2;

#pragma unroll
    for (int i = 0; i < 16; i++) {
        int idx = tid + i * 256;
        int row = idx >> 4;
        int c16 = idx & 15;
        uint4 v = *(const uint4*)(g_w1b + (size_t)row * FIN + c16 * 8);
        *(uint4*)(sB + row * G1_ST2 + c16 * 16) = v;
    }

    const uint32_t sAu = (uint32_t)__cvta_generic_to_shared(sA);
    const uint32_t sBu = (uint32_t)__cvta_generic_to_shared(sB);
    const int l15 = lane & 15;
    const int kgA = ((lane >> 4) & 1) * 16;
    uint32_t aAddr[2];
#pragma unroll
    for (int mt = 0; mt < 2; mt++)
        aAddr[mt] = sAu + (mw * 32 + mt * 16 + l15) * G1_ST2 + kgA;
    const int rB = (lane & 7) + ((lane >> 4) & 1) * 8;
    const int kgB = ((lane >> 3) & 1) * 16;
    uint32_t bAddr[4];
#pragma unroll
    for (int jp = 0; jp < 4; jp++)
        bAddr[jp] = sBu + (nw * 64 + jp * 16 + rB) * G1_ST2 + kgB;

    for (int tile = blockIdx.x; tile * 64 < NN; tile += G1_CTAS) {
        const int bm = tile * 64;
#pragma unroll
        for (int i = 0; i < 8; i++) {
            int idx = tid + i * 256;
            int row = idx >> 5;
            int c4 = idx & 31;
            float4 v = make_float4(0.f, 0.f, 0.f, 0.f);
            int grow = bm + row;
            if (grow < NN) v = *(const float4*)(x + (size_t)grow * FIN + c4 * 4);
            __nv_bfloat162 b0 = __floats2bfloat162_rn(v.x, v.y);
            __nv_bfloat162 b1 = __floats2bfloat162_rn(v.z, v.w);
            uint2 p = make_uint2(*(uint32_t*)&b0, *(uint32_t*)&b1);
            *(uint2*)(sA + row * G1_ST2 + c4 * 8) = p;
        }
        __syncthreads();

        float acc[2][8][4];
#pragma unroll
        for (int mt = 0; mt < 2; mt++)
#pragma unroll
            for (int j = 0; j < 8; j++)
#pragma unroll
                for (int q = 0; q < 4; q++) acc[mt][j][q] = 0.f;

#pragma unroll
        for (int kk = 0; kk < 8; kk++) {
            const uint32_t ko = kk * 32;
            uint32_t afr[2][4];
#pragma unroll
            for (int mt = 0; mt < 2; mt++)
                ldsm4(afr[mt][0], afr[mt][1], afr[mt][2], afr[mt][3], aAddr[mt] + ko);
            uint32_t bfr[8][2];
#pragma unroll
            for (int jp = 0; jp < 4; jp++)
                ldsm4(bfr[2 * jp][0], bfr[2 * jp][1], bfr[2 * jp + 1][0], bfr[2 * jp + 1][1],
                      bAddr[jp] + ko);
#pragma unroll
            for (int mt = 0; mt < 2; mt++)
#pragma unroll
                for (int j = 0; j < 8; j++) mma16816(acc[mt][j], afr[mt], bfr[j]);
        }

#pragma unroll
        for (int mt = 0; mt < 2; mt++) {
            const int r0 = bm + mw * 32 + mt * 16 + g;
            const int r1 = r0 + 8;
#pragma unroll
            for (int j = 0; j < 8; j++) {
                const int c = nw * 64 + j * 8 + t2;
                __nv_bfloat162 v0 = __floats2bfloat162_rn(acc[mt][j][0], acc[mt][j][1]);
                __nv_bfloat162 v1 = __floats2bfloat162_rn(acc[mt][j][2], acc[mt][j][3]);
                if (r0 < NN) *(uint32_t*)(g_xhb + (size_t)r0 * HC + c) = *(uint32_t*)&v0;
                if (r1 < NN) *(uint32_t*)(g_xhb + (size_t)r1 * HC + c) = *(uint32_t*)&v1;
            }
#pragma unroll
            for (int hh = 0; hh < 2; hh++) {
                float ps0 = 0.f, pd0 = 0.f, ps1 = 0.f, pd1 = 0.f;
#pragma unroll
                for (int jj = 0; jj < 4; jj++) {
                    const int j = hh * 4 + jj;
                    const int c = nw * 64 + j * 8 + t2;
                    float2 s2 = *(const float2*)(att_src + c);
                    float2 d2 = *(const float2*)(att_dst + c);
                    ps0 = fmaf(acc[mt][j][0], s2.x, fmaf(acc[mt][j][1], s2.y, ps0));
                    pd0 = fmaf(acc[mt][j][0], d2.x, fmaf(acc[mt][j][1], d2.y, pd0));
                    ps1 = fmaf(acc[mt][j][2], s2.x, fmaf(acc[mt][j][3], s2.y, ps1));
                    pd1 = fmaf(acc[mt][j][2], d2.x, fmaf(acc[mt][j][3], d2.y, pd1));
                }
                ps0 += __shfl_xor_sync(0xffffffffu, ps0, 1);
                pd0 += __shfl_xor_sync(0xffffffffu, pd0, 1);
                ps1 += __shfl_xor_sync(0xffffffffu, ps1, 1);
                pd1 += __shfl_xor_sync(0xffffffffu, pd1, 1);
                ps0 += __shfl_xor_sync(0xffffffffu, ps0, 2);
                pd0 += __shfl_xor_sync(0xffffffffu, pd0, 2);
                ps1 += __shfl_xor_sync(0xffffffffu, ps1, 2);
                pd1 += __shfl_xor_sync(0xffffffffu, pd1, 2);
                const int h = nw * 2 + hh;
                if ((lane & 3) == 0) {
                    if (r0 < NN) { g_as1[r0 * H1 + h] = ps0; g_ad1[r0 * H1 + h] = pd0; }
                    if (r1 < NN) { g_as1[r1 * H1 + h] = ps1; g_ad1[r1 * H1 + h] = pd1; }
                }
            }
        }
        __syncthreads();
    }
}

// ---------------- CSR build ------------------------------------------------------
__global__ void k_hist(const int* __restrict__ ei, int E) {
    int i4 = (blockIdx.x * blockDim.x + threadIdx.x) * 4;
    if (i4 + 4 <= E) {
        int4 d = *(const int4*)(ei + E + i4);
        atomicAdd(&g_deg[d.x], 1);
        atomicAdd(&g_deg[d.y], 1);
        atomicAdd(&g_deg[d.z], 1);
        atomicAdd(&g_deg[d.w], 1);
    } else {
        for (int e = i4; e < E; e++) atomicAdd(&g_deg[ei[E + e]], 1);
    }
}
__global__ void k_scan1() {
    __shared__ int s[256];
    int i = blockIdx.x * 256 + threadIdx.x;
    int v = (i < NN) ? g_deg[i] : 0;
    s[threadIdx.x] = v;
    __syncthreads();
    for (int o = 128; o; o >>= 1) {
        if (threadIdx.x < o) s[threadIdx.x] += s[threadIdx.x + o];
        __syncthreads();
    }
    if (threadIdx.x == 0) g_part[blockIdx.x] = s[0];
}
__global__ void k_scan2() {
    __shared__ int s[256];
    int t = threadIdx.x;
    int v = (t < NBLK) ? g_part[t] : 0;
    s[t] = v;
    __syncthreads();
    for (int o = 1; o < 256; o <<= 1) {
        int u = (t >= o) ? s[t - o] : 0;
        __syncthreads();
        s[t] += u;
        __syncthreads();
    }
    if (t < NBLK) g_part[t] = s[t] - v;
}
__global__ void k_scan3() {
    __shared__ int s[256];
    int t = threadIdx.x;
    int i = blockIdx.x * 256 + t;
    int v = (i < NN) ? g_deg[i] : 0;
    s[t] = v;
    __syncthreads();
    for (int o = 1; o < 256; o <<= 1) {
        int u = (t >= o) ? s[t - o] : 0;
        __syncthreads();
        s[t] += u;
        __syncthreads();
    }
    int base = g_part[blockIdx.x];
    if (i < NN) {
        int off = base + s[t] - v;
        g_off[i] = off;
        g_cur[i] = off;
        if (i == NN - 1) g_off[NN] = base + s[t];
    }
}
__global__ void k_scatter(const int* __restrict__ ei, int E) {
    int i4 = (blockIdx.x * blockDim.x + threadIdx.x) * 4;
    if (i4 + 4 <= E) {
        int4 s = *(const int4*)(ei + i4);
        int4 d = *(const int4*)(ei + E + i4);
        g_ssrc[atomicAdd(&g_cur[d.x], 1)] = s.x;
        g_ssrc[atomicAdd(&g_cur[d.y], 1)] = s.y;
        g_ssrc[atomicAdd(&g_cur[d.z], 1)] = s.z;
        g_ssrc[atomicAdd(&g_cur[d.w], 1)] = s.w;
    } else {
        for (int e = i4; e < E; e++) {
            int dd = ei[E + e];
            g_ssrc[atomicAdd(&g_cur[dd], 1)] = ei[e];
        }
    }
}

// ---------------- agg1 + fused layer-2 GEMV -------------------------------------
// block = 256 thr = 8 warps = 16 nodes; h1 staged in smem; warp0 does m16n16k256 HMMA
#define F_ST   264
#define F_ST2  (F_ST * 2)
__device__ __forceinline__ void edge_acc1(int s, float ad, int h, int vidx,
                                          const uint4* xb, __nv_bfloat162* acc,
                                          float& wsum) {
    const float a = g_as1[s * H1 + h];
    const uint4 v = xb[(size_t)s * 32 + vidx];
    const float w = exp_lrelu(a + ad);
    wsum += w;
    const __nv_bfloat162 w2 = __float2bfloat162_rn(w);
    const __nv_bfloat162* p = (const __nv_bfloat162*)&v;
#pragma unroll
    for (int j = 0; j < 4; j++) acc[j] = __hfma2(w2, p[j], acc[j]);
}

__global__ void k_agg1(const float* __restrict__ b1, const float* __restrict__ W2,
                       const float* __restrict__ att_src2,
                       const float* __restrict__ att_dst2) {
    __shared__ __nv_bfloat16 sH[16 * F_ST];     // 16 h1 rows, padded stride
    __shared__ __nv_bfloat16 sW2[16 * F_ST];    // W2^T zero-padded to 16 rows
    __shared__ float sS[16], sD[16];
    const int tid = threadIdx.x;
    const int warp = tid >> 5;
    const int lane = tid & 31;

    // stage W2^T (zero padded) + att vectors
    for (int i = tid; i < 16 * F_ST / 2; i += 256) ((uint32_t*)sW2)[i] = 0;
    if (tid < 16) { sS[tid] = 0.f; sD[tid] = 0.f; }
    __syncthreads();   // zero visible before scatter-fill
    for (int idx = tid; idx < HC * CO; idx += 256) {
        int k = idx / CO;
        int c = idx % CO;
        sW2[c * F_ST + k] = __float2bfloat16(W2[idx]);
    }
    if (tid < CO) { sS[tid] = att_src2[tid]; sD[tid] = att_dst2[tid]; }

    const int nA = blockIdx.x * 16 + warp * 2;
    const int nB = nA + 1;
    const int h = lane >> 2;
    const int q = lane & 3;
    const int vidx = h * 4 + q;
    const uint4* xb = (const uint4*)g_xhb;

    const float adA = g_ad1[nA * H1 + h];
    const float adB = g_ad1[nB * H1 + h];
    __nv_bfloat162 accA[4], accB[4];
    float wsumA, wsumB;
    {
        float wA = exp_lrelu(g_as1[nA * H1 + h] + adA);
        float wB = exp_lrelu(g_as1[nB * H1 + h] + adB);
        wsumA = wA; wsumB = wB;
        __nv_bfloat162 wA2 = __float2bfloat162_rn(wA);
        __nv_bfloat162 wB2 = __float2bfloat162_rn(wB);
        uint4 vA = xb[(size_t)nA * 32 + vidx];
        uint4 vB = xb[(size_t)nB * 32 + vidx];
        const __nv_bfloat162* pA = (const __nv_bfloat162*)&vA;
        const __nv_bfloat162* pB = (const __nv_bfloat162*)&vB;
#pragma unroll
        for (int j = 0; j < 4; j++) {
            accA[j] = __hmul2(wA2, pA[j]);
            accB[j] = __hmul2(wB2, pB[j]);
        }
    }

    int eA = g_off[nA];
    const int endA = g_off[nA + 1];
    int eB = endA;
    const int endB = g_off[nB + 1];

    while (eA + 2 <= endA && eB + 2 <= endB) {
        const int sA0 = g_ssrc[eA], sA1 = g_ssrc[eA + 1];
        const int sB0 = g_ssrc[eB], sB1 = g_ssrc[eB + 1];
        edge_acc1(sA0, adA, h, vidx, xb, accA, wsumA);
        edge_acc1(sB0, adB, h, vidx, xb, accB, wsumB);
        edge_acc1(sA1, adA, h, vidx, xb, accA, wsumA);
        edge_acc1(sB1, adB, h, vidx, xb, accB, wsumB);
        eA += 2; eB += 2;
    }
    for (; eA + 2 <= endA; eA += 2) {
        const int s0 = g_ssrc[eA], s1 = g_ssrc[eA + 1];
        edge_acc1(s0, adA, h, vidx, xb, accA, wsumA);
        edge_acc1(s1, adA, h, vidx, xb, accA, wsumA);
    }
    for (; eB + 2 <= endB; eB += 2) {
        const int s0 = g_ssrc[eB], s1 = g_ssrc[eB + 1];
        edge_acc1(s0, adB, h, vidx, xb, accB, wsumB);
        edge_acc1(s1, adB, h, vidx, xb, accB, wsumB);
    }
    if (eA < endA) edge_acc1(g_ssrc[eA], adA, h, vidx, xb, accA, wsumA);
    if (eB < endB) edge_acc1(g_ssrc[eB], adB, h, vidx, xb, accB, wsumB);

    // h1 -> smem (post elu, bf16)
    const int c0 = h * C1 + q * 8;
    float bias[8];
#pragma unroll
    for (int j = 0; j < 8; j++) bias[j] = b1[c0 + j];
    const float invA = 1.0f / wsumA;
    const float invB = 1.0f / wsumB;
    __nv_bfloat162 obA[4], obB[4];
#pragma unroll
    for (int j = 0; j < 4; j++) {
        float2 fA = __bfloat1622float2(accA[j]);
        float2 fB = __bfloat1622float2(accB[j]);
        obA[j] = __floats2bfloat162_rn(elu(fA.x * invA + bias[2 * j]),
                                       elu(fA.y * invA + bias[2 * j + 1]));
        obB[j] = __floats2bfloat162_rn(elu(fB.x * invB + bias[2 * j]),
                                       elu(fB.y * invB + bias[2 * j + 1]));
    }
    *(uint4*)(sH + (warp * 2) * F_ST + c0) = *(uint4*)obA;
    *(uint4*)(sH + (warp * 2 + 1) * F_ST + c0) = *(uint4*)obB;
    __syncthreads();

    // warp 0: m16 x n16 x k256 HMMA GEMV + fused attention epilogue
    if (warp == 0) {
        const int g = lane >> 2;
        const int t2 = (lane & 3) * 2;
        float a0c[4] = {0.f, 0.f, 0.f, 0.f};
        float a1c[4] = {0.f, 0.f, 0.f, 0.f};
        const char* cH = (const char*)sH;
        const char* cW = (const char*)sW2;
#pragma unroll
        for (int kk = 0; kk < 16; kk++) {
            const int k0 = kk * 16;
            uint32_t afr[4];
            afr[0] = *(const uint32_t*)(cH + g * F_ST2 + (k0 + t2) * 2);
            afr[1] = *(const uint32_t*)(cH + (g + 8) * F_ST2 + (k0 + t2) * 2);
            afr[2] = *(const uint32_t*)(cH + g * F_ST2 + (k0 + 8 + t2) * 2);
            afr[3] = *(const uint32_t*)(cH + (g + 8) * F_ST2 + (k0 + 8 + t2) * 2);
            uint32_t b0[2], b1r[2];
            b0[0] = *(const uint32_t*)(cW + g * F_ST2 + (k0 + t2) * 2);
            b0[1] = *(const uint32_t*)(cW + g * F_ST2 + (k0 + 8 + t2) * 2);
            b1r[0] = *(const uint32_t*)(cW + (8 + g) * F_ST2 + (k0 + t2) * 2);
            b1r[1] = *(const uint32_t*)(cW + (8 + g) * F_ST2 + (k0 + 8 + t2) * 2);
            mma16816(a0c, afr, b0);
            mma16816(a1c, afr, b1r);
        }
        const int r0 = blockIdx.x * 16 + g;
        const int r1 = r0 + 8;
        {
            __nv_bfloat162 p0 = __floats2bfloat162_rn(a0c[0], a0c[1]);
            __nv_bfloat162 p1 = __floats2bfloat162_rn(a1c[0], a1c[1]);
            *(uint32_t*)(g_xh2b + (size_t)r0 * 16 + t2) = *(uint32_t*)&p0;
            *(uint32_t*)(g_xh2b + (size_t)r0 * 16 + 8 + t2) = *(uint32_t*)&p1;
            __nv_bfloat162 p2 = __floats2bfloat162_rn(a0c[2], a0c[3]);
            __nv_bfloat162 p3 = __floats2bfloat162_rn(a1c[2], a1c[3]);
            *(uint32_t*)(g_xh2b + (size_t)r1 * 16 + t2) = *(uint32_t*)&p2;
            *(uint32_t*)(g_xh2b + (size_t)r1 * 16 + 8 + t2) = *(uint32_t*)&p3;
        }
        float s0x = sS[t2], s0y = sS[t2 + 1], s1x = sS[8 + t2], s1y = sS[9 + t2];
        float d0x = sD[t2], d0y = sD[t2 + 1], d1x = sD[8 + t2], d1y = sD[9 + t2];
        float ps0 = a0c[0] * s0x + a0c[1] * s0y + a1c[0] * s1x + a1c[1] * s1y;
        float pd0 = a0c[0] * d0x + a0c[1] * d0y + a1c[0] * d1x + a1c[1] * d1y;
        float ps1 = a0c[2] * s0x + a0c[3] * s0y + a1c[2] * s1x + a1c[3] * s1y;
        float pd1 = a0c[2] * d0x + a0c[3] * d0y + a1c[2] * d1x + a1c[3] * d1y;
        ps0 += __shfl_xor_sync(0xffffffffu, ps0, 1);
        pd0 += __shfl_xor_sync(0xffffffffu, pd0, 1);
        ps1 += __shfl_xor_sync(0xffffffffu, ps1, 1);
        pd1 += __shfl_xor_sync(0xffffffffu, pd1, 1);
        ps0 += __shfl_xor_sync(0xffffffffu, ps0, 2);
        pd0 += __shfl_xor_sync(0xffffffffu, pd0, 2);
        ps1 += __shfl_xor_sync(0xffffffffu, ps1, 2);
        pd1 += __shfl_xor_sync(0xffffffffu, pd1, 2);
        if ((lane & 3) == 0) {
            g_as2[r0] = ps0; g_ad2[r0] = pd0;
            g_as2[r1] = ps1; g_ad2[r1] = pd1;
        }
    }
}

// ---------------- layer-2 aggregation (bf16 payload) ------------------------------
__global__ void k_agg2(const int* __restrict__ batch, const float* __restrict__ b2) {
    int warp = threadIdx.x >> 5;
    int lane = threadIdx.x & 31;
    int n = blockIdx.x * 8 + warp;
    if (n >= NN) return;
    const int half = lane >> 4;
    const int i = lane & 15;
    const float ad = g_ad2[n];
    float wsum = 0.f, acc = 0.f;
    if (half == 0) {
        float w = exp_lrelu(g_as2[n] + ad);
        wsum = w;
        acc = w * __bfloat162float(g_xh2b[(size_t)n * 16 + i]);
    }
    const int beg = g_off[n], end = g_off[n + 1];
    for (int e = beg + half; e < end; e += 2) {
        const int s = g_ssrc[e];
        const float we = exp_lrelu(g_as2[s] + ad);
        wsum += we;
        acc = fmaf(we, __bfloat162float(g_xh2b[(size_t)s * 16 + i]), acc);
    }
    wsum += __shfl_xor_sync(0xffffffffu, wsum, 16);
    acc += __shfl_xor_sync(0xffffffffu, acc, 16);
    if (half == 0 && i < CO) {
        float out = elu(acc / wsum + b2[i]);
        atomicAdd(&g_sums[batch[n] * CO + i], out);
    }
    if (lane == 0) atomicAdd(&g_cnt[batch[n]], 1.0f);
}

// ---------------- mean + log_softmax ----------------------------------------------
__global__ void k_final(float* __restrict__ out) {
    int g = threadIdx.x;
    if (g >= NG) return;
    float inv = 1.0f / fmaxf(g_cnt[g], 1.0f);
    float v[CO];
    float mx = -1e30f;
#pragma unroll
    for (int c = 0; c < CO; c++) {
        v[c] = g_sums[g * CO + c] * inv;
        mx = fmaxf(mx, v[c]);
    }
    float s = 0.f;
#pragma unroll
    for (int c = 0; c < CO; c++) s += __expf(v[c] - mx);
    float lse = logf(s) + mx;
#pragma unroll
    for (int c = 0; c < CO; c++) out[g * CO + c] = v[c] - lse;
}

// ---------------- launcher ----------------------------------------------------------
extern "C" void kernel_launch(void* const* d_in, const int* in_sizes, int n_in,
                              void* d_out, int out_size) {
    const float* x        = (const float*)d_in[0];
    const int*   ei       = (const int*)d_in[1];
    const int*   batch    = (const int*)d_in[2];
    const float* W1       = (const float*)d_in[3];
    const float* att_src1 = (const float*)d_in[4];
    const float* att_dst1 = (const float*)d_in[5];
    const float* b1       = (const float*)d_in[6];
    const float* W2       = (const float*)d_in[7];
    const float* att_src2 = (const float*)d_in[8];
    const float* att_dst2 = (const float*)d_in[9];
    const float* b2       = (const float*)d_in[10];
    float* out = (float*)d_out;
    const int E = in_sizes[1] / 2;
    const int E4blk = ((E + 3) / 4 + 255) / 256;

    static cudaStream_t s1 = nullptr;
    static cudaEvent_t e0 = nullptr, e1 = nullptr;
    if (!s1) {
        cudaStreamCreateWithFlags(&s1, cudaStreamNonBlocking);
        cudaEventCreateWithFlags(&e0, cudaEventDisableTiming);
        cudaEventCreateWithFlags(&e1, cudaEventDisableTiming);
        cudaFuncSetAttribute(k_gemm1, cudaFuncAttributeMaxDynamicSharedMemorySize, G1_SMEM);
    }

    cudaEventRecord(e0, 0);
    k_zero<<<(NN + 255) / 256, 256>>>();
    k_hist<<<E4blk, 256>>>(ei, E);
    cudaStreamWaitEvent(s1, e0, 0);
    k_cvt_w<<<dim3(FIN / 32, HC / 32), dim3(32, 32), 0, s1>>>(W1);
    k_gemm1<<<G1_CTAS, 256, G1_SMEM, s1>>>(x, att_src1, att_dst1);
    cudaEventRecord(e1, s1);
    k_scan1<<<NBLK, 256>>>();
    k_scan2<<<1, 256>>>();
    k_scan3<<<NBLK, 256>>>();
    k_scatter<<<E4blk, 256>>>(ei, E);
    cudaStreamWaitEvent(0, e1, 0);
    k_agg1<<<NN / 16, 256>>>(b1, W2, att_src2, att_dst2);
    k_agg2<<<(NN + 7) / 8, 256>>>(batch, b2);
    k_final<<<1, NG>>>(out);
}